// round 10
// baseline (speedup 1.0000x reference)
#include <cuda_runtime.h>
#include <cuda_bf16.h>
#include <math.h>
#include <stdint.h>

#if defined(__CUDA_ARCH_FEAT_SM103_ALL) || defined(__CUDA_ARCH_FEAT_SM100_ALL) || \
    defined(__CUDA_ARCH_FEAT_SM101_ALL) || defined(__CUDA_ARCH_SPECIFIC__)
#define HAS_TCGEN05 1
#else
#define HAS_TCGEN05 0
#endif

#define NB 16
#define NT 2048
#define NK 128
#define NHD 8
#define HDIM 1024
#define DH 128
#define MS (NB*NK)      /* 2048 slot rows  */
#define MT (NB*NT)      /* 32768 token rows */

// ---------------- fp32 scratch ----------------
__device__ float g_queries[MS*HDIM];
__device__ float g_qh     [MS*HDIM];
__device__ float g_kvh    [(size_t)MT*2*HDIM];
__device__ float g_attnout[MS*HDIM];
__device__ float g_slots  [MS*HDIM];
__device__ float g_saqkv  [MS*3*HDIM];
__device__ float g_ctxout [MS*HDIM];

// ---------------- bf16 hi/lo scratch ----------------
__device__ __nv_bfloat16 a_proj_hi[(size_t)MT*HDIM];
__device__ __nv_bfloat16 a_proj_lo[(size_t)MT*HDIM];
__device__ __nv_bfloat16 a_act_hi [MS*HDIM];
__device__ __nv_bfloat16 a_act_lo [MS*HDIM];
__device__ __nv_bfloat16 w_qp_hi  [HDIM*HDIM];
__device__ __nv_bfloat16 w_qp_lo  [HDIM*HDIM];
__device__ __nv_bfloat16 w_cain_hi[3*HDIM*HDIM];
__device__ __nv_bfloat16 w_cain_lo[3*HDIM*HDIM];
__device__ __nv_bfloat16 w_caout_hi[HDIM*HDIM];
__device__ __nv_bfloat16 w_caout_lo[HDIM*HDIM];
__device__ __nv_bfloat16 w_sain_hi[3*HDIM*HDIM];
__device__ __nv_bfloat16 w_sain_lo[3*HDIM*HDIM];
__device__ __nv_bfloat16 w_saout_hi[HDIM*HDIM];
__device__ __nv_bfloat16 w_saout_lo[HDIM*HDIM];
__device__ __nv_bfloat16 a_act2_hi[MS*HDIM];
__device__ __nv_bfloat16 a_act2_lo[MS*HDIM];

__device__ __forceinline__ float* bufp(int id, float* ext) {
    switch (id) {
        case 1: return g_queries; case 2: return g_qh;
        case 3: return g_kvh;     case 5: return g_attnout;
        case 6: return g_slots;   case 7: return g_saqkv;
        case 9: return g_ctxout;  default: return ext;
    }
}
__device__ __forceinline__ __nv_bfloat16* bufb(int id) {
    switch (id) {
        case 0:  return a_proj_hi;  case 1:  return a_proj_lo;
        case 2:  return a_act_hi;   case 3:  return a_act_lo;
        case 4:  return w_qp_hi;    case 5:  return w_qp_lo;
        case 6:  return w_cain_hi;  case 7:  return w_cain_lo;
        case 8:  return w_caout_hi; case 9:  return w_caout_lo;
        case 10: return w_sain_hi;  case 11: return w_sain_lo;
        case 12: return w_saout_hi; case 13: return w_saout_lo;
        case 14: return a_act2_hi;  default: return a_act2_lo;
    }
}

// ---------------- helpers ----------------
__device__ __forceinline__ uint32_t smem_u32(const void* p) {
    uint32_t a;
    asm("{ .reg .u64 t; cvta.to.shared.u64 t, %1; cvt.u32.u64 %0, t; }" : "=r"(a) : "l"(p));
    return a;
}
#define SMEM_SWIZZLE_128B(o) ((o) ^ (((o) >> 3) & 0x70))
static constexpr unsigned long long SMEM_DESC_BASE_SW128 =
    (2ULL << 61) | (1ULL << 46) | (64ULL << 32) | (1ULL << 16);
#define MAKE_SMEM_DESC(a) (SMEM_DESC_BASE_SW128 | ((unsigned long long)((a) >> 4) & 0x3FFF))

#define MBARRIER_INIT(a, c) \
    asm volatile("mbarrier.init.shared.b64 [%0], %1;" :: "r"((uint32_t)(a)), "r"((uint32_t)(c)) : "memory")
#define MBARRIER_WAIT_PARITY(a, par) do { \
    uint32_t _m = (uint32_t)(a), _p = (uint32_t)(par), _d; \
    asm volatile("{ .reg .pred p; mbarrier.try_wait.parity.acquire.cta.shared::cta.b64 p, [%1], %2; selp.b32 %0,1,0,p; }" \
        : "=r"(_d) : "r"(_m), "r"(_p) : "memory"); \
    if (!_d) { \
        asm volatile("{ .reg .pred P1; WL_%=: mbarrier.try_wait.parity.acquire.cta.shared::cta.b64 P1, [%0], %1, 0x989680; @P1 bra.uni WD_%=; bra.uni WL_%=; WD_%=: }" \
            :: "r"(_m), "r"(_p) : "memory"); \
    } } while (0)

#if HAS_TCGEN05
__device__ __forceinline__ uint32_t elect_one_pred() {
    uint32_t p;
    asm volatile("{ .reg .pred p; elect.sync _|p, 0xFFFFFFFF; selp.b32 %0, 1, 0, p; }" : "=r"(p));
    return p;
}
#define TCGEN05_ALLOC(sa, n) \
    asm volatile("tcgen05.alloc.cta_group::1.sync.aligned.shared::cta.b32 [%0], %1;" \
        :: "r"((uint32_t)(sa)), "r"((uint32_t)(n)) : "memory")
#define TCGEN05_DEALLOC(t, n) \
    asm volatile("tcgen05.dealloc.cta_group::1.sync.aligned.b32 %0, %1;" :: "r"(t), "r"((uint32_t)(n)))
#define TCGEN05_RELINQ() \
    asm volatile("tcgen05.relinquish_alloc_permit.cta_group::1.sync.aligned;")
#define TCGEN05_COMMIT(mb) \
    asm volatile("tcgen05.commit.cta_group::1.mbarrier::arrive::one.shared::cluster.b64 [%0];" \
        :: "r"((uint32_t)(mb)) : "memory")
#define TCGEN05_FENCE_AFTER()  asm volatile("tcgen05.fence::after_thread_sync;" ::: "memory")
#define TCGEN05_FENCE_BEFORE() asm volatile("tcgen05.fence::before_thread_sync;" ::: "memory")
#define TCGEN05_WAIT_LD() asm volatile("tcgen05.wait::ld.sync.aligned;" ::: "memory")
#define TCGEN05_LD_X32(r, ta) \
    asm volatile("tcgen05.ld.sync.aligned.32x32b.x32.b32 " \
        "{%0,%1,%2,%3,%4,%5,%6,%7,%8,%9,%10,%11,%12,%13,%14,%15," \
        "%16,%17,%18,%19,%20,%21,%22,%23,%24,%25,%26,%27,%28,%29,%30,%31}, [%32];" \
        : "=r"((r)[0]),"=r"((r)[1]),"=r"((r)[2]),"=r"((r)[3]),"=r"((r)[4]),"=r"((r)[5]),"=r"((r)[6]),"=r"((r)[7]), \
          "=r"((r)[8]),"=r"((r)[9]),"=r"((r)[10]),"=r"((r)[11]),"=r"((r)[12]),"=r"((r)[13]),"=r"((r)[14]),"=r"((r)[15]), \
          "=r"((r)[16]),"=r"((r)[17]),"=r"((r)[18]),"=r"((r)[19]),"=r"((r)[20]),"=r"((r)[21]),"=r"((r)[22]),"=r"((r)[23]), \
          "=r"((r)[24]),"=r"((r)[25]),"=r"((r)[26]),"=r"((r)[27]),"=r"((r)[28]),"=r"((r)[29]),"=r"((r)[30]),"=r"((r)[31]) \
        : "r"(ta))

__device__ __forceinline__ void mma_f16_ss(uint32_t d, uint64_t ad, uint64_t bd,
                                           uint32_t idesc, uint32_t en) {
    asm volatile("{\n\t.reg .pred p;\n\tsetp.ne.u32 p, %4, 0;\n\t"
        "tcgen05.mma.cta_group::1.kind::f16 [%0], %1, %2, %3, {%5,%5,%5,%5}, p;\n\t}"
        :: "r"(d), "l"(ad), "l"(bd), "r"(idesc), "r"(en), "r"(0u) : "memory");
}
#endif // HAS_TCGEN05

template<int N> __device__ __forceinline__ void cp_async_wait() {
    asm volatile("cp.async.wait_group %0;" :: "n"(N) : "memory");
}
__device__ __forceinline__ void cp_async16(uint32_t s, const void* g) {
    asm volatile("cp.async.cg.shared.global [%0], [%1], 16;" :: "r"(s), "l"(g) : "memory");
}
__device__ __forceinline__ void cp_async_commit() {
    asm volatile("cp.async.commit_group;" ::: "memory");
}
__device__ __forceinline__ void st_cs_f4(float* p, float4 v) {
    asm volatile("st.global.cs.v4.f32 [%0], {%1,%2,%3,%4};"
        :: "l"(p), "f"(v.x), "f"(v.y), "f"(v.z), "f"(v.w) : "memory");
}

__device__ __forceinline__ void store_hilo4(__nv_bfloat16* hi, __nv_bfloat16* lo,
                                            size_t idx, float4 v) {
    __nv_bfloat16 h0 = __float2bfloat16(v.x), h1 = __float2bfloat16(v.y);
    __nv_bfloat16 h2 = __float2bfloat16(v.z), h3 = __float2bfloat16(v.w);
    __nv_bfloat16 l0 = __float2bfloat16(v.x - __bfloat162float(h0));
    __nv_bfloat16 l1 = __float2bfloat16(v.y - __bfloat162float(h1));
    __nv_bfloat16 l2 = __float2bfloat16(v.z - __bfloat162float(h2));
    __nv_bfloat16 l3 = __float2bfloat16(v.w - __bfloat162float(h3));
    __nv_bfloat162* hp = reinterpret_cast<__nv_bfloat162*>(hi + idx);
    __nv_bfloat162* lp = reinterpret_cast<__nv_bfloat162*>(lo + idx);
    hp[0] = __nv_bfloat162(h0, h1); hp[1] = __nv_bfloat162(h2, h3);
    lp[0] = __nv_bfloat162(l0, l1); lp[1] = __nv_bfloat162(l2, l3);
}

// ---------------- boundary decode ----------------
__device__ __forceinline__ void get_bounds(const int* __restrict__ w32,
                                           int blk, int& s, int& e) {
    bool is64 = (w32[1] == 0) && (w32[3] == 0);
    int a, b;
    if (is64) { a = w32[4*blk]; b = w32[4*blk + 2]; }
    else      { a = w32[2*blk]; b = w32[2*blk + 1]; }
    s = min(max(a, 0), NT);
    e = min(max(b, s), NT);
}
__device__ __forceinline__ float wred_max(float v) {
    #pragma unroll
    for (int o = 16; o; o >>= 1) v = fmaxf(v, __shfl_xor_sync(0xffffffffu, v, o));
    return v;
}
__device__ __forceinline__ float wred_sum(float v) {
    #pragma unroll
    for (int o = 16; o; o >>= 1) v += __shfl_xor_sync(0xffffffffu, v, o);
    return v;
}

// ---------------- fp32 -> bf16 hi/lo: projected ----------------
__global__ void conv_hilo(const float* __restrict__ src, int dstHiId, int dstLoId)
{
    __nv_bfloat16* hi = bufb(dstHiId);
    __nv_bfloat16* lo = bufb(dstLoId);
    size_t i = ((size_t)blockIdx.x * 256 + threadIdx.x) * 4;
    float4 v = *reinterpret_cast<const float4*>(src + i);
    store_hilo4(hi, lo, i, v);
}

// ---------------- fused weight hi/lo conversion (5 weights, 1 launch) ----------------
__global__ void conv_w_all(const float* __restrict__ qp, const float* __restrict__ cain,
                           const float* __restrict__ caout, const float* __restrict__ sain,
                           const float* __restrict__ saout)
{
    int blk = blockIdx.x;                       // 9216 blocks, 1024 elems each
    const float* src; __nv_bfloat16 *hi, *lo; int rel;
    if      (blk < 1024) { src = qp;    hi = w_qp_hi;    lo = w_qp_lo;    rel = blk; }
    else if (blk < 4096) { src = cain;  hi = w_cain_hi;  lo = w_cain_lo;  rel = blk - 1024; }
    else if (blk < 5120) { src = caout; hi = w_caout_hi; lo = w_caout_lo; rel = blk - 4096; }
    else if (blk < 8192) { src = sain;  hi = w_sain_hi;  lo = w_sain_lo;  rel = blk - 5120; }
    else                 { src = saout; hi = w_saout_hi; lo = w_saout_lo; rel = blk - 8192; }
    size_t i = ((size_t)rel * 256 + threadIdx.x) * 4;
    float4 v = *reinterpret_cast<const float4*>(src + i);
    store_hilo4(hi, lo, i, v);
}

// ---------------- tcgen05 bf16x3 GEMM, templated tile ----------------
// NTILE in {128, 256}; STAGES in {3, 2}. smem = STAGES*(32768+2*NTILE*128)+1024 = 197632 both.
#define GEMM_IDESC 0x8200490u
#define GEMM_SMEM 197632

template<int NTILE>
__device__ __forceinline__ void load_chunk(const __nv_bfloat16* ah, const __nv_bfloat16* al,
                                           const __nv_bfloat16* wh, const __nv_bfloat16* wl,
                                           uint32_t stage, int m0, int n0, int k0, int tid)
{
    const int TILE_W = NTILE * 128;
    #pragma unroll
    for (int u = 0; u < 4; ++u) {           // A hi/lo: 128 rows x 8 segs
        int idx = tid + u * 256;
        int row = idx >> 3, seg = idx & 7;
        uint32_t soff = SMEM_SWIZZLE_128B((uint32_t)(row * 128 + seg * 16));
        cp_async16(stage + soff,         ah + (size_t)(m0 + row) * HDIM + k0 + seg * 8);
        cp_async16(stage + 16384 + soff, al + (size_t)(m0 + row) * HDIM + k0 + seg * 8);
    }
    #pragma unroll
    for (int u = 0; u < NTILE/32; ++u) {    // W hi/lo: NTILE rows x 8 segs
        int idx = tid + u * 256;
        int row = idx >> 3, seg = idx & 7;
        uint32_t soff = SMEM_SWIZZLE_128B((uint32_t)(row * 128 + seg * 16));
        cp_async16(stage + 32768 + soff,          wh + (size_t)(n0 + row) * HDIM + k0 + seg * 8);
        cp_async16(stage + 32768 + TILE_W + soff, wl + (size_t)(n0 + row) * HDIM + k0 + seg * 8);
    }
    cp_async_commit();
}

template<int NTILE, int STAGES>
__global__ __launch_bounds__(256, 1)
void gemm_tc(int aHiId, int aLoId, int wHiId, int wLoId, size_t wOff,
             const float* __restrict__ bias, int Cid, int bfHiId, int bfLoId,
             int N, int streamC)
{
#if HAS_TCGEN05
    const int TILE_W  = NTILE * 128;
    const int STAGE_B = 32768 + 2 * TILE_W;
    extern __shared__ char dsm[];
    __shared__ __align__(8) unsigned long long s_mbar[3];
    __shared__ uint32_t s_tmem;
    __shared__ float bias_s[NTILE];

    const __nv_bfloat16* Ah = bufb(aHiId);
    const __nv_bfloat16* Al = bufb(aLoId);
    const __nv_bfloat16* Wh = bufb(wHiId) + wOff;
    const __nv_bfloat16* Wl = bufb(wLoId) + wOff;
    float* C = bufp(Cid, nullptr);
    __nv_bfloat16* bfHi = (bfHiId >= 0) ? bufb(bfHiId) : nullptr;
    __nv_bfloat16* bfLo = (bfHiId >= 0) ? bufb(bfLoId) : nullptr;

    int tid = threadIdx.x;
    int wid = tid >> 5, lane = tid & 31;
    int m0 = blockIdx.y * 128, n0 = blockIdx.x * NTILE;

    uint32_t tiles = (smem_u32(dsm) + 1023u) & ~1023u;
    uint32_t mb = smem_u32(&s_mbar[0]);

    if (wid == 0) TCGEN05_ALLOC(smem_u32(&s_tmem), NTILE);
    if (tid == 0) {
        #pragma unroll
        for (int s = 0; s < STAGES; ++s) MBARRIER_INIT(mb + s * 8, 1);
    }
    if (tid < NTILE) bias_s[tid] = bias[n0 + tid];
    __syncthreads();
    uint32_t tmem;
    asm volatile("ld.shared.b32 %0, [%1];" : "=r"(tmem) : "r"(smem_u32(&s_tmem)));

    #pragma unroll
    for (int s = 0; s < STAGES; ++s)
        load_chunk<NTILE>(Ah, Al, Wh, Wl, tiles + s * STAGE_B, m0, n0, s * 64, tid);

    int phase[STAGES];
    #pragma unroll
    for (int s = 0; s < STAGES; ++s) phase[s] = 0;

    // Deep pipeline: at iter k, consume chunk k; wait only for commit(k-1)
    // (dispatched LAST iteration, overlapping chunk k's MMA execution) before
    // refilling buffer (k-1)%STAGES with chunk k-1+STAGES.
    // Group math: chunk c lives in cp.async group c. While refills continue,
    // the newest committed group is a future chunk, so wait<1> suffices; on
    // the FINAL iteration the newest group IS chunk 15 -> must wait<0>.
    for (int k = 0; k < 16; ++k) {
        int b = k % STAGES;
        if (k == 15) cp_async_wait<0>();
        else         cp_async_wait<(STAGES >= 3) ? 1 : 0>();
        __syncthreads();
        if (wid == 0) {
            if (elect_one_pred()) {
                asm volatile("fence.proxy.async.shared::cta;" ::: "memory");
                uint32_t sb = tiles + b * STAGE_B;
                uint64_t dAh = MAKE_SMEM_DESC(sb);
                uint64_t dAl = MAKE_SMEM_DESC(sb + 16384);
                #pragma unroll
                for (int h = 0; h < NTILE/128; ++h) {
                    uint64_t dWh = MAKE_SMEM_DESC(sb + 32768 + h*16384);
                    uint64_t dWl = MAKE_SMEM_DESC(sb + 32768 + TILE_W + h*16384);
                    uint32_t dt = tmem + h * 128;
                    #pragma unroll
                    for (int s = 0; s < 4; ++s) {
                        uint32_t en0 = (k > 0 || s > 0) ? 1u : 0u;
                        mma_f16_ss(dt, dAh + s*2, dWh + s*2, GEMM_IDESC, en0);
                        mma_f16_ss(dt, dAl + s*2, dWh + s*2, GEMM_IDESC, 1u);
                        mma_f16_ss(dt, dAh + s*2, dWl + s*2, GEMM_IDESC, 1u);
                    }
                }
                TCGEN05_COMMIT(mb + b * 8);
            }
        }
        if (k >= 1 && (k - 1 + STAGES) < 16) {
            int pb = (k - 1) % STAGES;
            MBARRIER_WAIT_PARITY(mb + pb * 8, phase[pb]);
            phase[pb] ^= 1;
            load_chunk<NTILE>(Ah, Al, Wh, Wl, tiles + pb * STAGE_B, m0, n0,
                              (k - 1 + STAGES) * 64, tid);
        }
    }
    {   // wait for chunk 15's commit (tensor pipe is in-order -> all MMAs done)
        int bl = 15 % STAGES;
        MBARRIER_WAIT_PARITY(mb + bl * 8, phase[bl]);
    }
    TCGEN05_FENCE_AFTER();

    if (wid < 4) {
        int r = wid * 32 + lane;
        size_t rowbase = (size_t)(m0 + r) * N + n0;
        #pragma unroll
        for (int c0 = 0; c0 < NTILE; c0 += 32) {
            uint32_t regs[32];
            TCGEN05_LD_X32(regs, tmem + c0);
            TCGEN05_WAIT_LD();
            #pragma unroll
            for (int j = 0; j < 32; j += 4) {
                float4 o;
                o.x = __uint_as_float(regs[j+0]) + bias_s[c0+j+0];
                o.y = __uint_as_float(regs[j+1]) + bias_s[c0+j+1];
                o.z = __uint_as_float(regs[j+2]) + bias_s[c0+j+2];
                o.w = __uint_as_float(regs[j+3]) + bias_s[c0+j+3];
                if (C) {
                    float* cp = C + rowbase + c0 + j;
                    if (streamC) st_cs_f4(cp, o);
                    else *reinterpret_cast<float4*>(cp) = o;
                }
                if (bfHi) store_hilo4(bfHi, bfLo, rowbase + c0 + j, o);
            }
        }
        TCGEN05_FENCE_BEFORE();
    }
    __syncthreads();
    if (wid == 0) {
        TCGEN05_RELINQ();
        TCGEN05_DEALLOC(tmem, NTILE);
    }
#endif // HAS_TCGEN05
}

// ---------------- 1. bucket mean pool -> init hi/lo ----------------
__global__ void pool_kernel(const float* __restrict__ proj,
                            const int* __restrict__ bnd32,
                            const float* __restrict__ mask,
                            int hiId, int loId)
{
    int blk = blockIdx.x;
    int b = blk / NK;
    int s, e;
    get_bounds(bnd32, blk, s, e);
    float m = mask[blk];
    float4 a0 = make_float4(0.f, 0.f, 0.f, 0.f);
    float4 a1 = make_float4(0.f, 0.f, 0.f, 0.f);
    int cnt = e - s;
    if (m > 0.f && cnt > 0) {
        int t = s;
        for (; t + 1 < e; t += 2) {
            const float4* p0 = reinterpret_cast<const float4*>(proj + ((size_t)b*NT + t)*HDIM);
            const float4* p1 = reinterpret_cast<const float4*>(proj + ((size_t)b*NT + t + 1)*HDIM);
            float4 v0 = p0[threadIdx.x], v1 = p1[threadIdx.x];
            a0.x += v0.x; a0.y += v0.y; a0.z += v0.z; a0.w += v0.w;
            a1.x += v1.x; a1.y += v1.y; a1.z += v1.z; a1.w += v1.w;
        }
        if (t < e) {
            const float4* p0 = reinterpret_cast<const float4*>(proj + ((size_t)b*NT + t)*HDIM);
            float4 v0 = p0[threadIdx.x];
            a0.x += v0.x; a0.y += v0.y; a0.z += v0.z; a0.w += v0.w;
        }
        float inv = 1.f / (float)cnt;
        a0.x = (a0.x + a1.x) * inv; a0.y = (a0.y + a1.y) * inv;
        a0.z = (a0.z + a1.z) * inv; a0.w = (a0.w + a1.w) * inv;
    }
    store_hilo4(bufb(hiId), bufb(loId), (size_t)blk*HDIM + threadIdx.x*4, a0);
}

// ---------------- windowed cross attention -> attno hi/lo ----------------
__global__ void cross_attn_kernel(const int* __restrict__ bnd32,
                                  const float* __restrict__ mask,
                                  int hiId, int loId)
{
    int blk  = blockIdx.x;
    int b    = blk / NK;
    int head = threadIdx.x >> 5;
    int lane = threadIdx.x & 31;
    int s0, e0;
    get_bounds(bnd32, blk, s0, e0);
    int w = min(e0 - s0, 32);
    bool valid = (mask[blk] > 0.5f) && (w > 0);

    __shared__ __align__(16) float qsm[NHD][DH];
    const float4* qp4 = reinterpret_cast<const float4*>(g_qh + (size_t)blk*HDIM + head*DH);
    float4 qv = qp4[lane];
    qsm[head][lane*4+0] = qv.x; qsm[head][lane*4+1] = qv.y;
    qsm[head][lane*4+2] = qv.z; qsm[head][lane*4+3] = qv.w;
    __syncwarp();

    float sc = -INFINITY;
    if (valid && lane < w) {
        const float4* kp4 = reinterpret_cast<const float4*>(
            g_kvh + ((size_t)b*NT + s0 + lane) * (2*HDIM) + head*DH);
        const float4* q4 = reinterpret_cast<const float4*>(qsm[head]);
        float a = 0.f;
        #pragma unroll 8
        for (int d = 0; d < 32; ++d) {
            float4 kv = kp4[d], q2 = q4[d];
            a += q2.x*kv.x + q2.y*kv.y + q2.z*kv.z + q2.w*kv.w;
        }
        sc = a * 0.08838834764831845f;
    }
    float mx = wred_max(sc);
    float pj = (sc == -INFINITY) ? 0.f : __expf(sc - mx);
    float ss = wred_sum(pj);
    float p  = (valid && ss > 0.f) ? (pj / ss) : 0.f;

    float4 o = make_float4(0.f, 0.f, 0.f, 0.f);
    for (int t = 0; t < w; ++t) {
        float pt = __shfl_sync(0xffffffffu, p, t);
        const float4* vp4 = reinterpret_cast<const float4*>(
            g_kvh + ((size_t)b*NT + s0 + t) * (2*HDIM) + HDIM + head*DH);
        float4 v = vp4[lane];
        o.x += pt*v.x; o.y += pt*v.y; o.z += pt*v.z; o.w += pt*v.w;
    }
    store_hilo4(bufb(hiId), bufb(loId), (size_t)blk*HDIM + head*DH + lane*4, o);
}

// ---------------- fused residual-add + LayerNorm ----------------
__global__ void add_ln_kernel(int Xid, int Rid,
                              const float* __restrict__ g, const float* __restrict__ bet,
                              float* __restrict__ Oext, int Oid, int bfHiId, int bfLoId)
{
    const float* X = bufp(Xid, nullptr);
    const float* R = bufp(Rid, nullptr);
    float* out = bufp(Oid, Oext);
    int row = blockIdx.x;
    int tid = threadIdx.x;
    int lane = tid & 31, wid = tid >> 5;
    __shared__ float sm[8];

    float4 x = reinterpret_cast<const float4*>(X + (size_t)row*HDIM)[tid];
    float4 r = reinterpret_cast<const float4*>(R + (size_t)row*HDIM)[tid];
    x.x += r.x; x.y += r.y; x.z += r.z; x.w += r.w;

    float s = x.x + x.y + x.z + x.w;
    s = wred_sum(s);
    if (!lane) sm[wid] = s;
    __syncthreads();
    float tot = 0.f;
    #pragma unroll
    for (int i = 0; i < 8; ++i) tot += sm[i];
    float mean = tot * (1.f / HDIM);

    float d0 = x.x-mean, d1 = x.y-mean, d2 = x.z-mean, d3 = x.w-mean;
    float vloc = d0*d0 + d1*d1 + d2*d2 + d3*d3;
    __syncthreads();
    vloc = wred_sum(vloc);
    if (!lane) sm[wid] = vloc;
    __syncthreads();
    float var = 0.f;
    #pragma unroll
    for (int i = 0; i < 8; ++i) var += sm[i];
    var *= (1.f / HDIM);
    float inv = rsqrtf(var + 1e-5f);

    float4 gg = reinterpret_cast<const float4*>(g)[tid];
    float4 bb = reinterpret_cast<const float4*>(bet)[tid];
    float4 o;
    o.x = d0*inv*gg.x + bb.x;
    o.y = d1*inv*gg.y + bb.y;
    o.z = d2*inv*gg.z + bb.z;
    o.w = d3*inv*gg.w + bb.w;
    size_t idx = (size_t)row*HDIM + tid*4;
    *reinterpret_cast<float4*>(out + idx) = o;
    if (bfHiId >= 0) store_hilo4(bufb(bfHiId), bufb(bfLoId), idx, o);
}

// ---------------- causal self attention, block per (head, b) ----------------
#define SA_PAD 132
#define SA_SMEM ((2*NK*SA_PAD + 16*SA_PAD + 16*NK + NK) * 4)

__global__ __launch_bounds__(512, 1)
void self_attn_kernel(const float* __restrict__ mask, int hiId, int loId)
{
    extern __shared__ float sam[];
    float* Ksm = sam;
    float* Vsm = Ksm + NK*SA_PAD;
    float* qsm = Vsm + NK*SA_PAD;
    float* psm = qsm + 16*SA_PAD;
    float* msm = psm + 16*NK;

    int head = blockIdx.x, b = blockIdx.y;
    int tid = threadIdx.x, lane = tid & 31, w = tid >> 5;
    const float* base = g_saqkv + (size_t)(b*NK) * 3*HDIM;

    for (int idx = tid; idx < NK*DH; idx += 512) {
        int row = idx >> 7, col = idx & 127;
        Ksm[row*SA_PAD + col] = base[(size_t)row*3*HDIM +   HDIM + head*DH + col];
        Vsm[row*SA_PAD + col] = base[(size_t)row*3*HDIM + 2*HDIM + head*DH + col];
    }
    if (tid < NK) msm[tid] = mask[b*NK + tid];
    __syncthreads();

    __nv_bfloat16* ctxHi = bufb(hiId);
    __nv_bfloat16* ctxLo = bufb(loId);

    for (int qi = w; qi < NK; qi += 16) {
        float4 qv = *reinterpret_cast<const float4*>(
            base + (size_t)qi*3*HDIM + head*DH + lane*4);
        *reinterpret_cast<float4*>(qsm + w*SA_PAD + lane*4) = qv;
        __syncwarp();

        float sc[4];
        #pragma unroll
        for (int kk = 0; kk < 4; ++kk) {
            int j = lane + kk*32;
            float a = 0.f;
            const float* qr = qsm + w*SA_PAD;
            const float* kr = Ksm + j*SA_PAD;
            #pragma unroll 8
            for (int d = 0; d < 128; ++d) a += qr[d] * kr[d];
            bool ok = (j <= qi) && (msm[j] > 0.5f);
            sc[kk] = ok ? a * 0.08838834764831845f : -INFINITY;
        }
        float mx = fmaxf(fmaxf(sc[0], sc[1]), fmaxf(sc[2], sc[3]));
        mx = wred_max(mx);
        float psum = 0.f, pr[4];
        #pragma unroll
        for (int kk = 0; kk < 4; ++kk) {
            pr[kk] = (sc[kk] == -INFINITY) ? 0.f : __expf(sc[kk] - mx);
            psum += pr[kk];
        }
        psum = wred_sum(psum);
        float inv = (psum > 0.f) ? 1.f / psum : 0.f;
        #pragma unroll
        for (int kk = 0; kk < 4; ++kk)
            psm[w*NK + kk*32 + lane] = pr[kk] * inv;
        __syncwarp();

        float4 o = make_float4(0.f, 0.f, 0.f, 0.f);
        for (int j = 0; j <= qi; ++j) {
            float p = psm[w*NK + j];
            float4 v = *reinterpret_cast<const float4*>(Vsm + j*SA_PAD + lane*4);
            o.x += p*v.x; o.y += p*v.y; o.z += p*v.z; o.w += p*v.w;
        }
        store_hilo4(ctxHi, ctxLo, (size_t)(b*NK + qi)*HDIM + head*DH + lane*4, o);
        __syncwarp();
    }
}

// ---------------- launch ----------------
extern "C" void kernel_launch(void* const* d_in, const int* in_sizes, int n_in,
                              void* d_out, int out_size)
{
    const float* projected  = (const float*)d_in[0];
    const int*   bnd32      = (const int*)d_in[1];
    const float* slot_mask  = (const float*)d_in[2];
    const float* qp_w   = (const float*)d_in[3];
    const float* qp_b   = (const float*)d_in[4];
    const float* ca_in_w  = (const float*)d_in[5];
    const float* ca_in_b  = (const float*)d_in[6];
    const float* ca_out_w = (const float*)d_in[7];
    const float* ca_out_b = (const float*)d_in[8];
    const float* cn_g   = (const float*)d_in[9];
    const float* cn_b   = (const float*)d_in[10];
    const float* sa_in_w  = (const float*)d_in[11];
    const float* sa_in_b  = (const float*)d_in[12];
    const float* sa_out_w = (const float*)d_in[13];
    const float* sa_out_b = (const float*)d_in[14];
    const float* on_g   = (const float*)d_in[15];
    const float* on_b   = (const float*)d_in[16];
    float* out = (float*)d_out;

    static int attr_set = 0;
    if (!attr_set) {
        cudaFuncSetAttribute(gemm_tc<128,3>, cudaFuncAttributeMaxDynamicSharedMemorySize, GEMM_SMEM);
        cudaFuncSetAttribute(gemm_tc<256,2>, cudaFuncAttributeMaxDynamicSharedMemorySize, GEMM_SMEM);
        cudaFuncSetAttribute(self_attn_kernel, cudaFuncAttributeMaxDynamicSharedMemorySize, SA_SMEM);
        attr_set = 1;
    }

    // L1: proj hi/lo
    conv_hilo<<<(int)(((size_t)MT*HDIM)/1024), 256>>>(projected, 0, 1);
    // L2: all weights hi/lo (fused)
    conv_w_all<<<9216, 256>>>(qp_w, ca_in_w, ca_out_w, sa_in_w, sa_out_w);
    // L3: bucket mean pool -> act(2,3)
    pool_kernel<<<MS, 256>>>(projected, bnd32, slot_mask, 2, 3);
    // L4: queries = init @ qp_w^T -> fp32 id1 + act2(14,15)
    gemm_tc<128,3><<<dim3(HDIM/128, MS/128), 256, GEMM_SMEM>>>(2, 3, 4, 5, 0, qp_b, 1, 14, 15, HDIM, 0);
    // L5: qh = queries @ wq^T -> id2
    gemm_tc<128,3><<<dim3(HDIM/128, MS/128), 256, GEMM_SMEM>>>(14, 15, 6, 7, 0, ca_in_b, 2, -1, -1, HDIM, 0);
    // L6: kvh = projected @ [wk;wv]^T -> id3  (the big one)
    gemm_tc<256,2><<<dim3(2*HDIM/256, MT/128), 256, GEMM_SMEM>>>(0, 1, 6, 7, (size_t)HDIM*HDIM,
                                                                 ca_in_b + HDIM, 3, -1, -1, 2*HDIM, 1);
    // L7: windowed cross attention -> act(2,3)
    cross_attn_kernel<<<MS, 256>>>(bnd32, slot_mask, 2, 3);
    // L8: attn_out = attno @ ca_out_w^T -> id5
    gemm_tc<128,3><<<dim3(HDIM/128, MS/128), 256, GEMM_SMEM>>>(2, 3, 8, 9, 0, ca_out_b, 5, -1, -1, HDIM, 0);
    // L9: slots = LN(attn_out + queries) -> id6 + act2(14,15)
    add_ln_kernel<<<MS, 256>>>(5, 1, cn_g, cn_b, nullptr, 6, 14, 15);
    // L10: sa_qkv = slots @ sa_in_w^T -> id7
    gemm_tc<128,3><<<dim3(3*HDIM/128, MS/128), 256, GEMM_SMEM>>>(14, 15, 10, 11, 0, sa_in_b, 7, -1, -1, 3*HDIM, 0);
    // L11: causal self attention -> act(2,3)
    self_attn_kernel<<<dim3(NHD, NB), 512, SA_SMEM>>>(slot_mask, 2, 3);
    // L12: ctx_out = ctx @ sa_out_w^T -> id9
    gemm_tc<128,3><<<dim3(HDIM/128, MS/128), 256, GEMM_SMEM>>>(2, 3, 12, 13, 0, sa_out_b, 9, -1, -1, HDIM, 0);
    // L13: out = LN(ctx_out + slots)
    add_ln_kernel<<<MS, 256>>>(9, 6, on_g, on_b, out, -1, -1, -1);
}

// round 12
// speedup vs baseline: 1.0266x; 1.0266x over previous
#include <cuda_runtime.h>
#include <cuda_bf16.h>
#include <math.h>
#include <stdint.h>

#if defined(__CUDA_ARCH_FEAT_SM103_ALL) || defined(__CUDA_ARCH_FEAT_SM100_ALL) || \
    defined(__CUDA_ARCH_FEAT_SM101_ALL) || defined(__CUDA_ARCH_SPECIFIC__)
#define HAS_TCGEN05 1
#else
#define HAS_TCGEN05 0
#endif

#define NB 16
#define NT 2048
#define NK 128
#define NHD 8
#define HDIM 1024
#define DH 128
#define MS (NB*NK)      /* 2048 slot rows  */
#define MT (NB*NT)      /* 32768 token rows */

// ---------------- fp32 scratch ----------------
__device__ float g_queries[MS*HDIM];
__device__ float g_qh     [MS*HDIM];
__device__ float g_kvh    [(size_t)MT*2*HDIM];
__device__ float g_attnout[MS*HDIM];
__device__ float g_slots  [MS*HDIM];
__device__ float g_saqkv  [MS*3*HDIM];
__device__ float g_ctxout [MS*HDIM];

// ---------------- bf16 hi/lo scratch ----------------
__device__ __nv_bfloat16 a_proj_hi[(size_t)MT*HDIM];
__device__ __nv_bfloat16 a_proj_lo[(size_t)MT*HDIM];
__device__ __nv_bfloat16 a_act_hi [MS*HDIM];
__device__ __nv_bfloat16 a_act_lo [MS*HDIM];
__device__ __nv_bfloat16 w_qp_hi  [HDIM*HDIM];
__device__ __nv_bfloat16 w_qp_lo  [HDIM*HDIM];
__device__ __nv_bfloat16 w_cain_hi[3*HDIM*HDIM];
__device__ __nv_bfloat16 w_cain_lo[3*HDIM*HDIM];
__device__ __nv_bfloat16 w_caout_hi[HDIM*HDIM];
__device__ __nv_bfloat16 w_caout_lo[HDIM*HDIM];
__device__ __nv_bfloat16 w_sain_hi[3*HDIM*HDIM];
__device__ __nv_bfloat16 w_sain_lo[3*HDIM*HDIM];
__device__ __nv_bfloat16 w_saout_hi[HDIM*HDIM];
__device__ __nv_bfloat16 w_saout_lo[HDIM*HDIM];
__device__ __nv_bfloat16 a_act2_hi[MS*HDIM];
__device__ __nv_bfloat16 a_act2_lo[MS*HDIM];

__device__ __forceinline__ float* bufp(int id, float* ext) {
    switch (id) {
        case 1: return g_queries; case 2: return g_qh;
        case 3: return g_kvh;     case 5: return g_attnout;
        case 6: return g_slots;   case 7: return g_saqkv;
        case 9: return g_ctxout;  default: return ext;
    }
}
__device__ __forceinline__ __nv_bfloat16* bufb(int id) {
    switch (id) {
        case 0:  return a_proj_hi;  case 1:  return a_proj_lo;
        case 2:  return a_act_hi;   case 3:  return a_act_lo;
        case 4:  return w_qp_hi;    case 5:  return w_qp_lo;
        case 6:  return w_cain_hi;  case 7:  return w_cain_lo;
        case 8:  return w_caout_hi; case 9:  return w_caout_lo;
        case 10: return w_sain_hi;  case 11: return w_sain_lo;
        case 12: return w_saout_hi; case 13: return w_saout_lo;
        case 14: return a_act2_hi;  default: return a_act2_lo;
    }
}

// ---------------- helpers ----------------
__device__ __forceinline__ uint32_t smem_u32(const void* p) {
    uint32_t a;
    asm("{ .reg .u64 t; cvta.to.shared.u64 t, %1; cvt.u32.u64 %0, t; }" : "=r"(a) : "l"(p));
    return a;
}
#define SMEM_SWIZZLE_128B(o) ((o) ^ (((o) >> 3) & 0x70))
static constexpr unsigned long long SMEM_DESC_BASE_SW128 =
    (2ULL << 61) | (1ULL << 46) | (64ULL << 32) | (1ULL << 16);
#define MAKE_SMEM_DESC(a) (SMEM_DESC_BASE_SW128 | ((unsigned long long)((a) >> 4) & 0x3FFF))

#define MBARRIER_INIT(a, c) \
    asm volatile("mbarrier.init.shared.b64 [%0], %1;" :: "r"((uint32_t)(a)), "r"((uint32_t)(c)) : "memory")
#define MBARRIER_WAIT_PARITY(a, par) do { \
    uint32_t _m = (uint32_t)(a), _p = (uint32_t)(par), _d; \
    asm volatile("{ .reg .pred p; mbarrier.try_wait.parity.acquire.cta.shared::cta.b64 p, [%1], %2; selp.b32 %0,1,0,p; }" \
        : "=r"(_d) : "r"(_m), "r"(_p) : "memory"); \
    if (!_d) { \
        asm volatile("{ .reg .pred P1; WL_%=: mbarrier.try_wait.parity.acquire.cta.shared::cta.b64 P1, [%0], %1, 0x989680; @P1 bra.uni WD_%=; bra.uni WL_%=; WD_%=: }" \
            :: "r"(_m), "r"(_p) : "memory"); \
    } } while (0)

#if HAS_TCGEN05
__device__ __forceinline__ uint32_t elect_one_pred() {
    uint32_t p;
    asm volatile("{ .reg .pred p; elect.sync _|p, 0xFFFFFFFF; selp.b32 %0, 1, 0, p; }" : "=r"(p));
    return p;
}
#define TCGEN05_ALLOC(sa, n) \
    asm volatile("tcgen05.alloc.cta_group::1.sync.aligned.shared::cta.b32 [%0], %1;" \
        :: "r"((uint32_t)(sa)), "r"((uint32_t)(n)) : "memory")
#define TCGEN05_DEALLOC(t, n) \
    asm volatile("tcgen05.dealloc.cta_group::1.sync.aligned.b32 %0, %1;" :: "r"(t), "r"((uint32_t)(n)))
#define TCGEN05_RELINQ() \
    asm volatile("tcgen05.relinquish_alloc_permit.cta_group::1.sync.aligned;")
#define TCGEN05_COMMIT(mb) \
    asm volatile("tcgen05.commit.cta_group::1.mbarrier::arrive::one.shared::cluster.b64 [%0];" \
        :: "r"((uint32_t)(mb)) : "memory")
#define TCGEN05_FENCE_AFTER()  asm volatile("tcgen05.fence::after_thread_sync;" ::: "memory")
#define TCGEN05_FENCE_BEFORE() asm volatile("tcgen05.fence::before_thread_sync;" ::: "memory")
#define TCGEN05_WAIT_LD() asm volatile("tcgen05.wait::ld.sync.aligned;" ::: "memory")
#define TCGEN05_LD_X32(r, ta) \
    asm volatile("tcgen05.ld.sync.aligned.32x32b.x32.b32 " \
        "{%0,%1,%2,%3,%4,%5,%6,%7,%8,%9,%10,%11,%12,%13,%14,%15," \
        "%16,%17,%18,%19,%20,%21,%22,%23,%24,%25,%26,%27,%28,%29,%30,%31}, [%32];" \
        : "=r"((r)[0]),"=r"((r)[1]),"=r"((r)[2]),"=r"((r)[3]),"=r"((r)[4]),"=r"((r)[5]),"=r"((r)[6]),"=r"((r)[7]), \
          "=r"((r)[8]),"=r"((r)[9]),"=r"((r)[10]),"=r"((r)[11]),"=r"((r)[12]),"=r"((r)[13]),"=r"((r)[14]),"=r"((r)[15]), \
          "=r"((r)[16]),"=r"((r)[17]),"=r"((r)[18]),"=r"((r)[19]),"=r"((r)[20]),"=r"((r)[21]),"=r"((r)[22]),"=r"((r)[23]), \
          "=r"((r)[24]),"=r"((r)[25]),"=r"((r)[26]),"=r"((r)[27]),"=r"((r)[28]),"=r"((r)[29]),"=r"((r)[30]),"=r"((r)[31]) \
        : "r"(ta))

__device__ __forceinline__ void mma_f16_ss(uint32_t d, uint64_t ad, uint64_t bd,
                                           uint32_t idesc, uint32_t en) {
    asm volatile("{\n\t.reg .pred p;\n\tsetp.ne.u32 p, %4, 0;\n\t"
        "tcgen05.mma.cta_group::1.kind::f16 [%0], %1, %2, %3, {%5,%5,%5,%5}, p;\n\t}"
        :: "r"(d), "l"(ad), "l"(bd), "r"(idesc), "r"(en), "r"(0u) : "memory");
}
#endif // HAS_TCGEN05

template<int N> __device__ __forceinline__ void cp_async_wait() {
    asm volatile("cp.async.wait_group %0;" :: "n"(N) : "memory");
}
__device__ __forceinline__ void cp_async16(uint32_t s, const void* g) {
    asm volatile("cp.async.cg.shared.global [%0], [%1], 16;" :: "r"(s), "l"(g) : "memory");
}
__device__ __forceinline__ void cp_async_commit() {
    asm volatile("cp.async.commit_group;" ::: "memory");
}
__device__ __forceinline__ void st_cs_f4(float* p, float4 v) {
    asm volatile("st.global.cs.v4.f32 [%0], {%1,%2,%3,%4};"
        :: "l"(p), "f"(v.x), "f"(v.y), "f"(v.z), "f"(v.w) : "memory");
}

__device__ __forceinline__ void store_hilo4(__nv_bfloat16* hi, __nv_bfloat16* lo,
                                            size_t idx, float4 v) {
    __nv_bfloat16 h0 = __float2bfloat16(v.x), h1 = __float2bfloat16(v.y);
    __nv_bfloat16 h2 = __float2bfloat16(v.z), h3 = __float2bfloat16(v.w);
    __nv_bfloat16 l0 = __float2bfloat16(v.x - __bfloat162float(h0));
    __nv_bfloat16 l1 = __float2bfloat16(v.y - __bfloat162float(h1));
    __nv_bfloat16 l2 = __float2bfloat16(v.z - __bfloat162float(h2));
    __nv_bfloat16 l3 = __float2bfloat16(v.w - __bfloat162float(h3));
    __nv_bfloat162* hp = reinterpret_cast<__nv_bfloat162*>(hi + idx);
    __nv_bfloat162* lp = reinterpret_cast<__nv_bfloat162*>(lo + idx);
    hp[0] = __nv_bfloat162(h0, h1); hp[1] = __nv_bfloat162(h2, h3);
    lp[0] = __nv_bfloat162(l0, l1); lp[1] = __nv_bfloat162(l2, l3);
}

// ---------------- boundary decode ----------------
__device__ __forceinline__ void get_bounds(const int* __restrict__ w32,
                                           int blk, int& s, int& e) {
    bool is64 = (w32[1] == 0) && (w32[3] == 0);
    int a, b;
    if (is64) { a = w32[4*blk]; b = w32[4*blk + 2]; }
    else      { a = w32[2*blk]; b = w32[2*blk + 1]; }
    s = min(max(a, 0), NT);
    e = min(max(b, s), NT);
}
__device__ __forceinline__ float wred_max(float v) {
    #pragma unroll
    for (int o = 16; o; o >>= 1) v = fmaxf(v, __shfl_xor_sync(0xffffffffu, v, o));
    return v;
}
__device__ __forceinline__ float wred_sum(float v) {
    #pragma unroll
    for (int o = 16; o; o >>= 1) v += __shfl_xor_sync(0xffffffffu, v, o);
    return v;
}

// ---------------- fp32 -> bf16 hi/lo: projected ----------------
__global__ void conv_hilo(const float* __restrict__ src, int dstHiId, int dstLoId)
{
    __nv_bfloat16* hi = bufb(dstHiId);
    __nv_bfloat16* lo = bufb(dstLoId);
    size_t i = ((size_t)blockIdx.x * 256 + threadIdx.x) * 4;
    float4 v = *reinterpret_cast<const float4*>(src + i);
    store_hilo4(hi, lo, i, v);
}

// ---------------- fused weight hi/lo conversion (5 weights, 1 launch) ----------------
__global__ void conv_w_all(const float* __restrict__ qp, const float* __restrict__ cain,
                           const float* __restrict__ caout, const float* __restrict__ sain,
                           const float* __restrict__ saout)
{
    int blk = blockIdx.x;                       // 9216 blocks, 1024 elems each
    const float* src; __nv_bfloat16 *hi, *lo; int rel;
    if      (blk < 1024) { src = qp;    hi = w_qp_hi;    lo = w_qp_lo;    rel = blk; }
    else if (blk < 4096) { src = cain;  hi = w_cain_hi;  lo = w_cain_lo;  rel = blk - 1024; }
    else if (blk < 5120) { src = caout; hi = w_caout_hi; lo = w_caout_lo; rel = blk - 4096; }
    else if (blk < 8192) { src = sain;  hi = w_sain_hi;  lo = w_sain_lo;  rel = blk - 5120; }
    else                 { src = saout; hi = w_saout_hi; lo = w_saout_lo; rel = blk - 8192; }
    size_t i = ((size_t)rel * 256 + threadIdx.x) * 4;
    float4 v = *reinterpret_cast<const float4*>(src + i);
    store_hilo4(hi, lo, i, v);
}

// ---------------- tcgen05 bf16x3 GEMM, templated tile ----------------
// NTILE in {128, 256}; STAGES in {3, 2}. smem = STAGES*(32768+2*NTILE*128)+1024 = 197632 both.
#define GEMM_IDESC 0x8200490u
#define GEMM_SMEM 197632

template<int NTILE>
__device__ __forceinline__ void load_chunk(const __nv_bfloat16* ah, const __nv_bfloat16* al,
                                           const __nv_bfloat16* wh, const __nv_bfloat16* wl,
                                           uint32_t stage, int m0, int n0, int k0, int tid)
{
    const int TILE_W = NTILE * 128;
    #pragma unroll
    for (int u = 0; u < 4; ++u) {           // A hi/lo: 128 rows x 8 segs
        int idx = tid + u * 256;
        int row = idx >> 3, seg = idx & 7;
        uint32_t soff = SMEM_SWIZZLE_128B((uint32_t)(row * 128 + seg * 16));
        cp_async16(stage + soff,         ah + (size_t)(m0 + row) * HDIM + k0 + seg * 8);
        cp_async16(stage + 16384 + soff, al + (size_t)(m0 + row) * HDIM + k0 + seg * 8);
    }
    #pragma unroll
    for (int u = 0; u < NTILE/32; ++u) {    // W hi/lo: NTILE rows x 8 segs
        int idx = tid + u * 256;
        int row = idx >> 3, seg = idx & 7;
        uint32_t soff = SMEM_SWIZZLE_128B((uint32_t)(row * 128 + seg * 16));
        cp_async16(stage + 32768 + soff,          wh + (size_t)(n0 + row) * HDIM + k0 + seg * 8);
        cp_async16(stage + 32768 + TILE_W + soff, wl + (size_t)(n0 + row) * HDIM + k0 + seg * 8);
    }
    cp_async_commit();
}

template<int NTILE, int STAGES>
__global__ __launch_bounds__(256, 1)
void gemm_tc(int aHiId, int aLoId, int wHiId, int wLoId, size_t wOff,
             const float* __restrict__ bias, int Cid, int bfHiId, int bfLoId,
             int N, int streamC)
{
#if HAS_TCGEN05
    const int TILE_W  = NTILE * 128;
    const int STAGE_B = 32768 + 2 * TILE_W;
    extern __shared__ char dsm[];
    __shared__ __align__(8) unsigned long long s_mbar[3];
    __shared__ uint32_t s_tmem;
    __shared__ float bias_s[NTILE];

    const __nv_bfloat16* Ah = bufb(aHiId);
    const __nv_bfloat16* Al = bufb(aLoId);
    const __nv_bfloat16* Wh = bufb(wHiId) + wOff;
    const __nv_bfloat16* Wl = bufb(wLoId) + wOff;
    float* C = bufp(Cid, nullptr);
    __nv_bfloat16* bfHi = (bfHiId >= 0) ? bufb(bfHiId) : nullptr;
    __nv_bfloat16* bfLo = (bfHiId >= 0) ? bufb(bfLoId) : nullptr;

    int tid = threadIdx.x;
    int wid = tid >> 5, lane = tid & 31;
    int m0 = blockIdx.y * 128, n0 = blockIdx.x * NTILE;

    uint32_t tiles = (smem_u32(dsm) + 1023u) & ~1023u;
    uint32_t mb = smem_u32(&s_mbar[0]);

    if (wid == 0) TCGEN05_ALLOC(smem_u32(&s_tmem), NTILE);
    if (tid == 0) {
        #pragma unroll
        for (int s = 0; s < STAGES; ++s) MBARRIER_INIT(mb + s * 8, 1);
    }
    if (tid < NTILE) bias_s[tid] = bias[n0 + tid];
    __syncthreads();
    uint32_t tmem;
    asm volatile("ld.shared.b32 %0, [%1];" : "=r"(tmem) : "r"(smem_u32(&s_tmem)));

    #pragma unroll
    for (int s = 0; s < STAGES; ++s)
        load_chunk<NTILE>(Ah, Al, Wh, Wl, tiles + s * STAGE_B, m0, n0, s * 64, tid);

    int phase[STAGES];
    #pragma unroll
    for (int s = 0; s < STAGES; ++s) phase[s] = 0;

    // Deep pipeline: at iter k, consume chunk k; wait only for commit(k-1)
    // (dispatched LAST iteration, overlapping chunk k's MMA execution) before
    // refilling buffer (k-1)%STAGES with chunk k-1+STAGES.
    // Group math: chunk c lives in cp.async group c. While refills continue,
    // the newest committed group is a future chunk, so wait<1> suffices; on
    // the FINAL iteration the newest group IS chunk 15 -> must wait<0>.
    for (int k = 0; k < 16; ++k) {
        int b = k % STAGES;
        if (k == 15) cp_async_wait<0>();
        else         cp_async_wait<(STAGES >= 3) ? 1 : 0>();
        __syncthreads();
        if (wid == 0) {
            if (elect_one_pred()) {
                asm volatile("fence.proxy.async.shared::cta;" ::: "memory");
                uint32_t sb = tiles + b * STAGE_B;
                uint64_t dAh = MAKE_SMEM_DESC(sb);
                uint64_t dAl = MAKE_SMEM_DESC(sb + 16384);
                #pragma unroll
                for (int h = 0; h < NTILE/128; ++h) {
                    uint64_t dWh = MAKE_SMEM_DESC(sb + 32768 + h*16384);
                    uint64_t dWl = MAKE_SMEM_DESC(sb + 32768 + TILE_W + h*16384);
                    uint32_t dt = tmem + h * 128;
                    #pragma unroll
                    for (int s = 0; s < 4; ++s) {
                        uint32_t en0 = (k > 0 || s > 0) ? 1u : 0u;
                        mma_f16_ss(dt, dAh + s*2, dWh + s*2, GEMM_IDESC, en0);
                        mma_f16_ss(dt, dAl + s*2, dWh + s*2, GEMM_IDESC, 1u);
                        mma_f16_ss(dt, dAh + s*2, dWl + s*2, GEMM_IDESC, 1u);
                    }
                }
                TCGEN05_COMMIT(mb + b * 8);
            }
        }
        if (k >= 1 && (k - 1 + STAGES) < 16) {
            int pb = (k - 1) % STAGES;
            MBARRIER_WAIT_PARITY(mb + pb * 8, phase[pb]);
            phase[pb] ^= 1;
            load_chunk<NTILE>(Ah, Al, Wh, Wl, tiles + pb * STAGE_B, m0, n0,
                              (k - 1 + STAGES) * 64, tid);
        }
    }
    {   // wait for chunk 15's commit (tensor pipe is in-order -> all MMAs done)
        int bl = 15 % STAGES;
        MBARRIER_WAIT_PARITY(mb + bl * 8, phase[bl]);
    }
    TCGEN05_FENCE_AFTER();

    if (wid < 4) {
        int r = wid * 32 + lane;
        size_t rowbase = (size_t)(m0 + r) * N + n0;
        #pragma unroll
        for (int c0 = 0; c0 < NTILE; c0 += 32) {
            uint32_t regs[32];
            TCGEN05_LD_X32(regs, tmem + c0);
            TCGEN05_WAIT_LD();
            #pragma unroll
            for (int j = 0; j < 32; j += 4) {
                float4 o;
                o.x = __uint_as_float(regs[j+0]) + bias_s[c0+j+0];
                o.y = __uint_as_float(regs[j+1]) + bias_s[c0+j+1];
                o.z = __uint_as_float(regs[j+2]) + bias_s[c0+j+2];
                o.w = __uint_as_float(regs[j+3]) + bias_s[c0+j+3];
                if (C) {
                    float* cp = C + rowbase + c0 + j;
                    if (streamC) st_cs_f4(cp, o);
                    else *reinterpret_cast<float4*>(cp) = o;
                }
                if (bfHi) store_hilo4(bfHi, bfLo, rowbase + c0 + j, o);
            }
        }
        TCGEN05_FENCE_BEFORE();
    }
    __syncthreads();
    if (wid == 0) {
        TCGEN05_RELINQ();
        TCGEN05_DEALLOC(tmem, NTILE);
    }
#endif // HAS_TCGEN05
}

// ---------------- 1. bucket mean pool -> init hi/lo ----------------
__global__ void pool_kernel(const float* __restrict__ proj,
                            const int* __restrict__ bnd32,
                            const float* __restrict__ mask,
                            int hiId, int loId)
{
    int blk = blockIdx.x;
    int b = blk / NK;
    int s, e;
    get_bounds(bnd32, blk, s, e);
    float m = mask[blk];
    float4 a0 = make_float4(0.f, 0.f, 0.f, 0.f);
    float4 a1 = make_float4(0.f, 0.f, 0.f, 0.f);
    int cnt = e - s;
    if (m > 0.f && cnt > 0) {
        int t = s;
        for (; t + 1 < e; t += 2) {
            const float4* p0 = reinterpret_cast<const float4*>(proj + ((size_t)b*NT + t)*HDIM);
            const float4* p1 = reinterpret_cast<const float4*>(proj + ((size_t)b*NT + t + 1)*HDIM);
            float4 v0 = p0[threadIdx.x], v1 = p1[threadIdx.x];
            a0.x += v0.x; a0.y += v0.y; a0.z += v0.z; a0.w += v0.w;
            a1.x += v1.x; a1.y += v1.y; a1.z += v1.z; a1.w += v1.w;
        }
        if (t < e) {
            const float4* p0 = reinterpret_cast<const float4*>(proj + ((size_t)b*NT + t)*HDIM);
            float4 v0 = p0[threadIdx.x];
            a0.x += v0.x; a0.y += v0.y; a0.z += v0.z; a0.w += v0.w;
        }
        float inv = 1.f / (float)cnt;
        a0.x = (a0.x + a1.x) * inv; a0.y = (a0.y + a1.y) * inv;
        a0.z = (a0.z + a1.z) * inv; a0.w = (a0.w + a1.w) * inv;
    }
    store_hilo4(bufb(hiId), bufb(loId), (size_t)blk*HDIM + threadIdx.x*4, a0);
}

// ---------------- windowed cross attention -> attno hi/lo ----------------
__global__ void cross_attn_kernel(const int* __restrict__ bnd32,
                                  const float* __restrict__ mask,
                                  int hiId, int loId)
{
    int blk  = blockIdx.x;
    int b    = blk / NK;
    int head = threadIdx.x >> 5;
    int lane = threadIdx.x & 31;
    int s0, e0;
    get_bounds(bnd32, blk, s0, e0);
    int w = min(e0 - s0, 32);
    bool valid = (mask[blk] > 0.5f) && (w > 0);

    __shared__ __align__(16) float qsm[NHD][DH];
    const float4* qp4 = reinterpret_cast<const float4*>(g_qh + (size_t)blk*HDIM + head*DH);
    float4 qv = qp4[lane];
    qsm[head][lane*4+0] = qv.x; qsm[head][lane*4+1] = qv.y;
    qsm[head][lane*4+2] = qv.z; qsm[head][lane*4+3] = qv.w;
    __syncwarp();

    float sc = -INFINITY;
    if (valid && lane < w) {
        const float4* kp4 = reinterpret_cast<const float4*>(
            g_kvh + ((size_t)b*NT + s0 + lane) * (2*HDIM) + head*DH);
        const float4* q4 = reinterpret_cast<const float4*>(qsm[head]);
        float a = 0.f;
        #pragma unroll 8
        for (int d = 0; d < 32; ++d) {
            float4 kv = kp4[d], q2 = q4[d];
            a += q2.x*kv.x + q2.y*kv.y + q2.z*kv.z + q2.w*kv.w;
        }
        sc = a * 0.08838834764831845f;
    }
    float mx = wred_max(sc);
    float pj = (sc == -INFINITY) ? 0.f : __expf(sc - mx);
    float ss = wred_sum(pj);
    float p  = (valid && ss > 0.f) ? (pj / ss) : 0.f;

    float4 o = make_float4(0.f, 0.f, 0.f, 0.f);
    for (int t = 0; t < w; ++t) {
        float pt = __shfl_sync(0xffffffffu, p, t);
        const float4* vp4 = reinterpret_cast<const float4*>(
            g_kvh + ((size_t)b*NT + s0 + t) * (2*HDIM) + HDIM + head*DH);
        float4 v = vp4[lane];
        o.x += pt*v.x; o.y += pt*v.y; o.z += pt*v.z; o.w += pt*v.w;
    }
    store_hilo4(bufb(hiId), bufb(loId), (size_t)blk*HDIM + head*DH + lane*4, o);
}

// ---------------- fused residual-add + LayerNorm ----------------
__global__ void add_ln_kernel(int Xid, int Rid,
                              const float* __restrict__ g, const float* __restrict__ bet,
                              float* __restrict__ Oext, int Oid, int bfHiId, int bfLoId)
{
    const float* X = bufp(Xid, nullptr);
    const float* R = bufp(Rid, nullptr);
    float* out = bufp(Oid, Oext);
    int row = blockIdx.x;
    int tid = threadIdx.x;
    int lane = tid & 31, wid = tid >> 5;
    __shared__ float sm[8];

    float4 x = reinterpret_cast<const float4*>(X + (size_t)row*HDIM)[tid];
    float4 r = reinterpret_cast<const float4*>(R + (size_t)row*HDIM)[tid];
    x.x += r.x; x.y += r.y; x.z += r.z; x.w += r.w;

    float s = x.x + x.y + x.z + x.w;
    s = wred_sum(s);
    if (!lane) sm[wid] = s;
    __syncthreads();
    float tot = 0.f;
    #pragma unroll
    for (int i = 0; i < 8; ++i) tot += sm[i];
    float mean = tot * (1.f / HDIM);

    float d0 = x.x-mean, d1 = x.y-mean, d2 = x.z-mean, d3 = x.w-mean;
    float vloc = d0*d0 + d1*d1 + d2*d2 + d3*d3;
    __syncthreads();
    vloc = wred_sum(vloc);
    if (!lane) sm[wid] = vloc;
    __syncthreads();
    float var = 0.f;
    #pragma unroll
    for (int i = 0; i < 8; ++i) var += sm[i];
    var *= (1.f / HDIM);
    float inv = rsqrtf(var + 1e-5f);

    float4 gg = reinterpret_cast<const float4*>(g)[tid];
    float4 bb = reinterpret_cast<const float4*>(bet)[tid];
    float4 o;
    o.x = d0*inv*gg.x + bb.x;
    o.y = d1*inv*gg.y + bb.y;
    o.z = d2*inv*gg.z + bb.z;
    o.w = d3*inv*gg.w + bb.w;
    size_t idx = (size_t)row*HDIM + tid*4;
    *reinterpret_cast<float4*>(out + idx) = o;
    if (bfHiId >= 0) store_hilo4(bufb(bfHiId), bufb(bfLoId), idx, o);
}

// ---------------- causal self attention, block per (head, b) ----------------
#define SA_PAD 132
#define SA_SMEM ((2*NK*SA_PAD + 16*SA_PAD + 16*NK + NK) * 4)

__global__ __launch_bounds__(512, 1)
void self_attn_kernel(const float* __restrict__ mask, int hiId, int loId)
{
    extern __shared__ float sam[];
    float* Ksm = sam;
    float* Vsm = Ksm + NK*SA_PAD;
    float* qsm = Vsm + NK*SA_PAD;
    float* psm = qsm + 16*SA_PAD;
    float* msm = psm + 16*NK;

    int head = blockIdx.x, b = blockIdx.y;
    int tid = threadIdx.x, lane = tid & 31, w = tid >> 5;
    const float* base = g_saqkv + (size_t)(b*NK) * 3*HDIM;

    for (int idx = tid; idx < NK*DH; idx += 512) {
        int row = idx >> 7, col = idx & 127;
        Ksm[row*SA_PAD + col] = base[(size_t)row*3*HDIM +   HDIM + head*DH + col];
        Vsm[row*SA_PAD + col] = base[(size_t)row*3*HDIM + 2*HDIM + head*DH + col];
    }
    if (tid < NK) msm[tid] = mask[b*NK + tid];
    __syncthreads();

    __nv_bfloat16* ctxHi = bufb(hiId);
    __nv_bfloat16* ctxLo = bufb(loId);

    for (int qi = w; qi < NK; qi += 16) {
        float4 qv = *reinterpret_cast<const float4*>(
            base + (size_t)qi*3*HDIM + head*DH + lane*4);
        *reinterpret_cast<float4*>(qsm + w*SA_PAD + lane*4) = qv;
        __syncwarp();

        float sc[4];
        #pragma unroll
        for (int kk = 0; kk < 4; ++kk) {
            int j = lane + kk*32;
            float a = 0.f;
            const float* qr = qsm + w*SA_PAD;
            const float* kr = Ksm + j*SA_PAD;
            #pragma unroll 8
            for (int d = 0; d < 128; ++d) a += qr[d] * kr[d];
            bool ok = (j <= qi) && (msm[j] > 0.5f);
            sc[kk] = ok ? a * 0.08838834764831845f : -INFINITY;
        }
        float mx = fmaxf(fmaxf(sc[0], sc[1]), fmaxf(sc[2], sc[3]));
        mx = wred_max(mx);
        float psum = 0.f, pr[4];
        #pragma unroll
        for (int kk = 0; kk < 4; ++kk) {
            pr[kk] = (sc[kk] == -INFINITY) ? 0.f : __expf(sc[kk] - mx);
            psum += pr[kk];
        }
        psum = wred_sum(psum);
        float inv = (psum > 0.f) ? 1.f / psum : 0.f;
        #pragma unroll
        for (int kk = 0; kk < 4; ++kk)
            psm[w*NK + kk*32 + lane] = pr[kk] * inv;
        __syncwarp();

        float4 o = make_float4(0.f, 0.f, 0.f, 0.f);
        for (int j = 0; j <= qi; ++j) {
            float p = psm[w*NK + j];
            float4 v = *reinterpret_cast<const float4*>(Vsm + j*SA_PAD + lane*4);
            o.x += p*v.x; o.y += p*v.y; o.z += p*v.z; o.w += p*v.w;
        }
        store_hilo4(ctxHi, ctxLo, (size_t)(b*NK + qi)*HDIM + head*DH + lane*4, o);
        __syncwarp();
    }
}

// ---------------- launch ----------------
extern "C" void kernel_launch(void* const* d_in, const int* in_sizes, int n_in,
                              void* d_out, int out_size)
{
    const float* projected  = (const float*)d_in[0];
    const int*   bnd32      = (const int*)d_in[1];
    const float* slot_mask  = (const float*)d_in[2];
    const float* qp_w   = (const float*)d_in[3];
    const float* qp_b   = (const float*)d_in[4];
    const float* ca_in_w  = (const float*)d_in[5];
    const float* ca_in_b  = (const float*)d_in[6];
    const float* ca_out_w = (const float*)d_in[7];
    const float* ca_out_b = (const float*)d_in[8];
    const float* cn_g   = (const float*)d_in[9];
    const float* cn_b   = (const float*)d_in[10];
    const float* sa_in_w  = (const float*)d_in[11];
    const float* sa_in_b  = (const float*)d_in[12];
    const float* sa_out_w = (const float*)d_in[13];
    const float* sa_out_b = (const float*)d_in[14];
    const float* on_g   = (const float*)d_in[15];
    const float* on_b   = (const float*)d_in[16];
    float* out = (float*)d_out;

    static int attr_set = 0;
    static cudaStream_t s1 = nullptr, s2 = nullptr;
    static cudaEvent_t evF = nullptr, evProj = nullptr, evPool = nullptr;
    if (!attr_set) {
        cudaFuncSetAttribute(gemm_tc<128,3>, cudaFuncAttributeMaxDynamicSharedMemorySize, GEMM_SMEM);
        cudaFuncSetAttribute(gemm_tc<256,2>, cudaFuncAttributeMaxDynamicSharedMemorySize, GEMM_SMEM);
        cudaFuncSetAttribute(self_attn_kernel, cudaFuncAttributeMaxDynamicSharedMemorySize, SA_SMEM);
        cudaStreamCreateWithFlags(&s1, cudaStreamNonBlocking);
        cudaStreamCreateWithFlags(&s2, cudaStreamNonBlocking);
        cudaEventCreateWithFlags(&evF,    cudaEventDisableTiming);
        cudaEventCreateWithFlags(&evProj, cudaEventDisableTiming);
        cudaEventCreateWithFlags(&evPool, cudaEventDisableTiming);
        attr_set = 1;
    }

    // ---- fork: s1 runs the big proj conversion, s2 runs pool; default runs
    //      weight conversion + the two query-side GEMMs. Join before L6.
    cudaEventRecord(evF, 0);
    cudaStreamWaitEvent(s1, evF, 0);
    cudaStreamWaitEvent(s2, evF, 0);

    // s1: proj hi/lo (needed only by the big kvh GEMM)
    conv_hilo<<<(int)(((size_t)MT*HDIM)/1024), 256, 0, s1>>>(projected, 0, 1);
    cudaEventRecord(evProj, s1);

    // s2: bucket mean pool -> act(2,3) (needed by L4)
    pool_kernel<<<MS, 256, 0, s2>>>(projected, bnd32, slot_mask, 2, 3);
    cudaEventRecord(evPool, s2);

    // default: all weights hi/lo (fused)
    conv_w_all<<<9216, 256>>>(qp_w, ca_in_w, ca_out_w, sa_in_w, sa_out_w);

    // L4: queries = init @ qp_w^T -> fp32 id1 + act2(14,15)   (needs pool)
    cudaStreamWaitEvent(0, evPool, 0);
    gemm_tc<128,3><<<dim3(HDIM/128, MS/128), 256, GEMM_SMEM>>>(2, 3, 4, 5, 0, qp_b, 1, 14, 15, HDIM, 0);
    // L5: qh = queries @ wq^T -> id2
    gemm_tc<128,3><<<dim3(HDIM/128, MS/128), 256, GEMM_SMEM>>>(14, 15, 6, 7, 0, ca_in_b, 2, -1, -1, HDIM, 0);

    // L6: kvh = projected @ [wk;wv]^T -> id3  (needs proj conv)
    cudaStreamWaitEvent(0, evProj, 0);
    gemm_tc<256,2><<<dim3(2*HDIM/256, MT/128), 256, GEMM_SMEM>>>(0, 1, 6, 7, (size_t)HDIM*HDIM,
                                                                 ca_in_b + HDIM, 3, -1, -1, 2*HDIM, 1);
    // L7: windowed cross attention -> act(2,3)
    cross_attn_kernel<<<MS, 256>>>(bnd32, slot_mask, 2, 3);
    // L8: attn_out = attno @ ca_out_w^T -> id5
    gemm_tc<128,3><<<dim3(HDIM/128, MS/128), 256, GEMM_SMEM>>>(2, 3, 8, 9, 0, ca_out_b, 5, -1, -1, HDIM, 0);
    // L9: slots = LN(attn_out + queries) -> id6 + act2(14,15)
    add_ln_kernel<<<MS, 256>>>(5, 1, cn_g, cn_b, nullptr, 6, 14, 15);
    // L10: sa_qkv = slots @ sa_in_w^T -> id7
    gemm_tc<128,3><<<dim3(3*HDIM/128, MS/128), 256, GEMM_SMEM>>>(14, 15, 10, 11, 0, sa_in_b, 7, -1, -1, 3*HDIM, 0);
    // L11: causal self attention -> act(2,3)
    self_attn_kernel<<<dim3(NHD, NB), 512, SA_SMEM>>>(slot_mask, 2, 3);
    // L12: ctx_out = ctx @ sa_out_w^T -> id9
    gemm_tc<128,3><<<dim3(HDIM/128, MS/128), 256, GEMM_SMEM>>>(2, 3, 12, 13, 0, sa_out_b, 9, -1, -1, HDIM, 0);
    // L13: out = LN(ctx_out + slots)
    add_ln_kernel<<<MS, 256>>>(9, 6, on_g, on_b, out, -1, -1, -1);
}

// round 15
// speedup vs baseline: 1.1138x; 1.0849x over previous
#include <cuda_runtime.h>
#include <cuda_bf16.h>
#include <math.h>
#include <stdint.h>

#if defined(__CUDA_ARCH_FEAT_SM103_ALL) || defined(__CUDA_ARCH_FEAT_SM100_ALL) || \
    defined(__CUDA_ARCH_FEAT_SM101_ALL) || defined(__CUDA_ARCH_SPECIFIC__)
#define HAS_TCGEN05 1
#else
#define HAS_TCGEN05 0
#endif

#define NB 16
#define NT 2048
#define NK 128
#define NHD 8
#define HDIM 1024
#define DH 128
#define MS (NB*NK)      /* 2048 slot rows  */
#define MT (NB*NT)      /* 32768 token rows */

// ---------------- fp32 scratch ----------------
__device__ float g_queries[MS*HDIM];
__device__ float g_qh     [MS*HDIM];
__device__ float g_kvh    [(size_t)MT*2*HDIM];
__device__ float g_attnout[MS*HDIM];
__device__ float g_slots  [MS*HDIM];
__device__ float g_saqkv  [MS*3*HDIM];
__device__ float g_ctxout [MS*HDIM];

// ---------------- bf16 hi/lo scratch ----------------
__device__ __nv_bfloat16 a_proj_hi[(size_t)MT*HDIM];
__device__ __nv_bfloat16 a_proj_lo[(size_t)MT*HDIM];
__device__ __nv_bfloat16 a_act_hi [MS*HDIM];
__device__ __nv_bfloat16 a_act_lo [MS*HDIM];
__device__ __nv_bfloat16 w_qp_hi  [HDIM*HDIM];
__device__ __nv_bfloat16 w_qp_lo  [HDIM*HDIM];
__device__ __nv_bfloat16 w_cain_hi[3*HDIM*HDIM];
__device__ __nv_bfloat16 w_cain_lo[3*HDIM*HDIM];
__device__ __nv_bfloat16 w_caout_hi[HDIM*HDIM];
__device__ __nv_bfloat16 w_caout_lo[HDIM*HDIM];
__device__ __nv_bfloat16 w_sain_hi[3*HDIM*HDIM];
__device__ __nv_bfloat16 w_sain_lo[3*HDIM*HDIM];
__device__ __nv_bfloat16 w_saout_hi[HDIM*HDIM];
__device__ __nv_bfloat16 w_saout_lo[HDIM*HDIM];
__device__ __nv_bfloat16 a_act2_hi[MS*HDIM];
__device__ __nv_bfloat16 a_act2_lo[MS*HDIM];

__device__ __forceinline__ float* bufp(int id, float* ext) {
    switch (id) {
        case 1: return g_queries; case 2: return g_qh;
        case 3: return g_kvh;     case 5: return g_attnout;
        case 6: return g_slots;   case 7: return g_saqkv;
        case 9: return g_ctxout;  default: return ext;
    }
}
__device__ __forceinline__ __nv_bfloat16* bufb(int id) {
    switch (id) {
        case 0:  return a_proj_hi;  case 1:  return a_proj_lo;
        case 2:  return a_act_hi;   case 3:  return a_act_lo;
        case 4:  return w_qp_hi;    case 5:  return w_qp_lo;
        case 6:  return w_cain_hi;  case 7:  return w_cain_lo;
        case 8:  return w_caout_hi; case 9:  return w_caout_lo;
        case 10: return w_sain_hi;  case 11: return w_sain_lo;
        case 12: return w_saout_hi; case 13: return w_saout_lo;
        case 14: return a_act2_hi;  default: return a_act2_lo;
    }
}

// ---------------- helpers ----------------
__device__ __forceinline__ uint32_t smem_u32(const void* p) {
    uint32_t a;
    asm("{ .reg .u64 t; cvta.to.shared.u64 t, %1; cvt.u32.u64 %0, t; }" : "=r"(a) : "l"(p));
    return a;
}
#define SMEM_SWIZZLE_128B(o) ((o) ^ (((o) >> 3) & 0x70))
static constexpr unsigned long long SMEM_DESC_BASE_SW128 =
    (2ULL << 61) | (1ULL << 46) | (64ULL << 32) | (1ULL << 16);
#define MAKE_SMEM_DESC(a) (SMEM_DESC_BASE_SW128 | ((unsigned long long)((a) >> 4) & 0x3FFF))

#define MBARRIER_INIT(a, c) \
    asm volatile("mbarrier.init.shared.b64 [%0], %1;" :: "r"((uint32_t)(a)), "r"((uint32_t)(c)) : "memory")
#define MBARRIER_WAIT_PARITY(a, par) do { \
    uint32_t _m = (uint32_t)(a), _p = (uint32_t)(par), _d; \
    asm volatile("{ .reg .pred p; mbarrier.try_wait.parity.acquire.cta.shared::cta.b64 p, [%1], %2; selp.b32 %0,1,0,p; }" \
        : "=r"(_d) : "r"(_m), "r"(_p) : "memory"); \
    if (!_d) { \
        asm volatile("{ .reg .pred P1; WL_%=: mbarrier.try_wait.parity.acquire.cta.shared::cta.b64 P1, [%0], %1, 0x989680; @P1 bra.uni WD_%=; bra.uni WL_%=; WD_%=: }" \
            :: "r"(_m), "r"(_p) : "memory"); \
    } } while (0)

#if HAS_TCGEN05
__device__ __forceinline__ uint32_t elect_one_pred() {
    uint32_t p;
    asm volatile("{ .reg .pred p; elect.sync _|p, 0xFFFFFFFF; selp.b32 %0, 1, 0, p; }" : "=r"(p));
    return p;
}
#define TCGEN05_ALLOC(sa, n) \
    asm volatile("tcgen05.alloc.cta_group::1.sync.aligned.shared::cta.b32 [%0], %1;" \
        :: "r"((uint32_t)(sa)), "r"((uint32_t)(n)) : "memory")
#define TCGEN05_DEALLOC(t, n) \
    asm volatile("tcgen05.dealloc.cta_group::1.sync.aligned.b32 %0, %1;" :: "r"(t), "r"((uint32_t)(n)))
#define TCGEN05_RELINQ() \
    asm volatile("tcgen05.relinquish_alloc_permit.cta_group::1.sync.aligned;")
#define TCGEN05_COMMIT(mb) \
    asm volatile("tcgen05.commit.cta_group::1.mbarrier::arrive::one.shared::cluster.b64 [%0];" \
        :: "r"((uint32_t)(mb)) : "memory")
#define TCGEN05_FENCE_AFTER()  asm volatile("tcgen05.fence::after_thread_sync;" ::: "memory")
#define TCGEN05_FENCE_BEFORE() asm volatile("tcgen05.fence::before_thread_sync;" ::: "memory")
#define TCGEN05_WAIT_LD() asm volatile("tcgen05.wait::ld.sync.aligned;" ::: "memory")
#define TCGEN05_LD_X32(r, ta) \
    asm volatile("tcgen05.ld.sync.aligned.32x32b.x32.b32 " \
        "{%0,%1,%2,%3,%4,%5,%6,%7,%8,%9,%10,%11,%12,%13,%14,%15," \
        "%16,%17,%18,%19,%20,%21,%22,%23,%24,%25,%26,%27,%28,%29,%30,%31}, [%32];" \
        : "=r"((r)[0]),"=r"((r)[1]),"=r"((r)[2]),"=r"((r)[3]),"=r"((r)[4]),"=r"((r)[5]),"=r"((r)[6]),"=r"((r)[7]), \
          "=r"((r)[8]),"=r"((r)[9]),"=r"((r)[10]),"=r"((r)[11]),"=r"((r)[12]),"=r"((r)[13]),"=r"((r)[14]),"=r"((r)[15]), \
          "=r"((r)[16]),"=r"((r)[17]),"=r"((r)[18]),"=r"((r)[19]),"=r"((r)[20]),"=r"((r)[21]),"=r"((r)[22]),"=r"((r)[23]), \
          "=r"((r)[24]),"=r"((r)[25]),"=r"((r)[26]),"=r"((r)[27]),"=r"((r)[28]),"=r"((r)[29]),"=r"((r)[30]),"=r"((r)[31]) \
        : "r"(ta))

__device__ __forceinline__ void mma_f16_ss(uint32_t d, uint64_t ad, uint64_t bd,
                                           uint32_t idesc, uint32_t en) {
    asm volatile("{\n\t.reg .pred p;\n\tsetp.ne.u32 p, %4, 0;\n\t"
        "tcgen05.mma.cta_group::1.kind::f16 [%0], %1, %2, %3, {%5,%5,%5,%5}, p;\n\t}"
        :: "r"(d), "l"(ad), "l"(bd), "r"(idesc), "r"(en), "r"(0u) : "memory");
}
#endif // HAS_TCGEN05

template<int N> __device__ __forceinline__ void cp_async_wait() {
    asm volatile("cp.async.wait_group %0;" :: "n"(N) : "memory");
}
__device__ __forceinline__ void cp_async16(uint32_t s, const void* g) {
    asm volatile("cp.async.cg.shared.global [%0], [%1], 16;" :: "r"(s), "l"(g) : "memory");
}
__device__ __forceinline__ void cp_async_commit() {
    asm volatile("cp.async.commit_group;" ::: "memory");
}
__device__ __forceinline__ void st_cs_f4(float* p, float4 v) {
    asm volatile("st.global.cs.v4.f32 [%0], {%1,%2,%3,%4};"
        :: "l"(p), "f"(v.x), "f"(v.y), "f"(v.z), "f"(v.w) : "memory");
}

__device__ __forceinline__ void store_hilo4(__nv_bfloat16* hi, __nv_bfloat16* lo,
                                            size_t idx, float4 v) {
    __nv_bfloat16 h0 = __float2bfloat16(v.x), h1 = __float2bfloat16(v.y);
    __nv_bfloat16 h2 = __float2bfloat16(v.z), h3 = __float2bfloat16(v.w);
    __nv_bfloat16 l0 = __float2bfloat16(v.x - __bfloat162float(h0));
    __nv_bfloat16 l1 = __float2bfloat16(v.y - __bfloat162float(h1));
    __nv_bfloat16 l2 = __float2bfloat16(v.z - __bfloat162float(h2));
    __nv_bfloat16 l3 = __float2bfloat16(v.w - __bfloat162float(h3));
    __nv_bfloat162* hp = reinterpret_cast<__nv_bfloat162*>(hi + idx);
    __nv_bfloat162* lp = reinterpret_cast<__nv_bfloat162*>(lo + idx);
    hp[0] = __nv_bfloat162(h0, h1); hp[1] = __nv_bfloat162(h2, h3);
    lp[0] = __nv_bfloat162(l0, l1); lp[1] = __nv_bfloat162(l2, l3);
}

// ---------------- boundary decode ----------------
__device__ __forceinline__ void get_bounds(const int* __restrict__ w32,
                                           int blk, int& s, int& e) {
    bool is64 = (w32[1] == 0) && (w32[3] == 0);
    int a, b;
    if (is64) { a = w32[4*blk]; b = w32[4*blk + 2]; }
    else      { a = w32[2*blk]; b = w32[2*blk + 1]; }
    s = min(max(a, 0), NT);
    e = min(max(b, s), NT);
}
__device__ __forceinline__ float wred_max(float v) {
    #pragma unroll
    for (int o = 16; o; o >>= 1) v = fmaxf(v, __shfl_xor_sync(0xffffffffu, v, o));
    return v;
}
__device__ __forceinline__ float wred_sum(float v) {
    #pragma unroll
    for (int o = 16; o; o >>= 1) v += __shfl_xor_sync(0xffffffffu, v, o);
    return v;
}

// ---------------- fp32 -> bf16 hi/lo: projected ----------------
__global__ void conv_hilo(const float* __restrict__ src, int dstHiId, int dstLoId)
{
    __nv_bfloat16* hi = bufb(dstHiId);
    __nv_bfloat16* lo = bufb(dstLoId);
    size_t i = ((size_t)blockIdx.x * 256 + threadIdx.x) * 4;
    float4 v = *reinterpret_cast<const float4*>(src + i);
    store_hilo4(hi, lo, i, v);
}

// ---------------- fused weight hi/lo conversion (5 weights, 1 launch) ----------------
__global__ void conv_w_all(const float* __restrict__ qp, const float* __restrict__ cain,
                           const float* __restrict__ caout, const float* __restrict__ sain,
                           const float* __restrict__ saout)
{
    int blk = blockIdx.x;                       // 9216 blocks, 1024 elems each
    const float* src; __nv_bfloat16 *hi, *lo; int rel;
    if      (blk < 1024) { src = qp;    hi = w_qp_hi;    lo = w_qp_lo;    rel = blk; }
    else if (blk < 4096) { src = cain;  hi = w_cain_hi;  lo = w_cain_lo;  rel = blk - 1024; }
    else if (blk < 5120) { src = caout; hi = w_caout_hi; lo = w_caout_lo; rel = blk - 4096; }
    else if (blk < 8192) { src = sain;  hi = w_sain_hi;  lo = w_sain_lo;  rel = blk - 5120; }
    else                 { src = saout; hi = w_saout_hi; lo = w_saout_lo; rel = blk - 8192; }
    size_t i = ((size_t)rel * 256 + threadIdx.x) * 4;
    float4 v = *reinterpret_cast<const float4*>(src + i);
    store_hilo4(hi, lo, i, v);
}

// ---------------- tcgen05 bf16x3 GEMM, templated tile ----------------
// NTILE in {128, 256}; STAGES in {3, 2}. smem = STAGES*(32768+2*NTILE*128)+1024 = 197632 both.
#define GEMM_IDESC 0x8200490u
#define GEMM_SMEM 197632

template<int NTILE>
__device__ __forceinline__ void load_chunk(const __nv_bfloat16* ah, const __nv_bfloat16* al,
                                           const __nv_bfloat16* wh, const __nv_bfloat16* wl,
                                           uint32_t stage, int m0, int n0, int k0, int tid)
{
    const int TILE_W = NTILE * 128;
    #pragma unroll
    for (int u = 0; u < 4; ++u) {           // A hi/lo: 128 rows x 8 segs
        int idx = tid + u * 256;
        int row = idx >> 3, seg = idx & 7;
        uint32_t soff = SMEM_SWIZZLE_128B((uint32_t)(row * 128 + seg * 16));
        cp_async16(stage + soff,         ah + (size_t)(m0 + row) * HDIM + k0 + seg * 8);
        cp_async16(stage + 16384 + soff, al + (size_t)(m0 + row) * HDIM + k0 + seg * 8);
    }
    #pragma unroll
    for (int u = 0; u < NTILE/32; ++u) {    // W hi/lo: NTILE rows x 8 segs
        int idx = tid + u * 256;
        int row = idx >> 3, seg = idx & 7;
        uint32_t soff = SMEM_SWIZZLE_128B((uint32_t)(row * 128 + seg * 16));
        cp_async16(stage + 32768 + soff,          wh + (size_t)(n0 + row) * HDIM + k0 + seg * 8);
        cp_async16(stage + 32768 + TILE_W + soff, wl + (size_t)(n0 + row) * HDIM + k0 + seg * 8);
    }
    cp_async_commit();
}

template<int NTILE, int STAGES>
__global__ __launch_bounds__(256, 1)
void gemm_tc(int aHiId, int aLoId, int wHiId, int wLoId, size_t wOff,
             const float* __restrict__ bias, int Cid, int bfHiId, int bfLoId,
             int N, int streamC)
{
#if HAS_TCGEN05
    const int TILE_W  = NTILE * 128;
    const int STAGE_B = 32768 + 2 * TILE_W;
    extern __shared__ char dsm[];
    __shared__ __align__(8) unsigned long long s_mbar[3];
    __shared__ uint32_t s_tmem;
    __shared__ float bias_s[NTILE];

    const __nv_bfloat16* Ah = bufb(aHiId);
    const __nv_bfloat16* Al = bufb(aLoId);
    const __nv_bfloat16* Wh = bufb(wHiId) + wOff;
    const __nv_bfloat16* Wl = bufb(wLoId) + wOff;
    float* C = bufp(Cid, nullptr);
    __nv_bfloat16* bfHi = (bfHiId >= 0) ? bufb(bfHiId) : nullptr;
    __nv_bfloat16* bfLo = (bfHiId >= 0) ? bufb(bfLoId) : nullptr;

    int tid = threadIdx.x;
    int wid = tid >> 5, lane = tid & 31;
    int m0 = blockIdx.y * 128, n0 = blockIdx.x * NTILE;

    uint32_t tiles = (smem_u32(dsm) + 1023u) & ~1023u;
    uint32_t mb = smem_u32(&s_mbar[0]);

    if (wid == 0) TCGEN05_ALLOC(smem_u32(&s_tmem), NTILE);
    if (tid == 0) {
        #pragma unroll
        for (int s = 0; s < STAGES; ++s) MBARRIER_INIT(mb + s * 8, 1);
    }
    if (tid < NTILE) bias_s[tid] = bias[n0 + tid];
    __syncthreads();
    uint32_t tmem;
    asm volatile("ld.shared.b32 %0, [%1];" : "=r"(tmem) : "r"(smem_u32(&s_tmem)));

    #pragma unroll
    for (int s = 0; s < STAGES; ++s)
        load_chunk<NTILE>(Ah, Al, Wh, Wl, tiles + s * STAGE_B, m0, n0, s * 64, tid);

    int phase[STAGES];
    #pragma unroll
    for (int s = 0; s < STAGES; ++s) phase[s] = 0;

    // Two verified loop orderings, chosen at compile time:
    //  - STAGES==2 (big, load-bound): distance-2 prefetch — wait commit(k)
    //    right after dispatch, then refill buffer k%2 with chunk k+2 (R6-fast).
    //  - STAGES==3 (small, latency-bound): deferred wait — after dispatching
    //    chunk k, wait commit(k-1) (overlaps chunk k's MMAs), refill with
    //    chunk k+2 (R10-fast).
    // Both: chunk c lives in cp.async group c; wait<1> suffices while a newer
    // group is outstanding, but the FINAL iteration's chunk is the newest
    // group -> wait<0> (closes the R7 race).
    for (int k = 0; k < 16; ++k) {
        int b = k % STAGES;
        if (k == 15) cp_async_wait<0>();
        else         cp_async_wait<1>();
        __syncthreads();
        if (wid == 0) {
            if (elect_one_pred()) {
                asm volatile("fence.proxy.async.shared::cta;" ::: "memory");
                uint32_t sb = tiles + b * STAGE_B;
                uint64_t dAh = MAKE_SMEM_DESC(sb);
                uint64_t dAl = MAKE_SMEM_DESC(sb + 16384);
                #pragma unroll
                for (int h = 0; h < NTILE/128; ++h) {
                    uint64_t dWh = MAKE_SMEM_DESC(sb + 32768 + h*16384);
                    uint64_t dWl = MAKE_SMEM_DESC(sb + 32768 + TILE_W + h*16384);
                    uint32_t dt = tmem + h * 128;
                    #pragma unroll
                    for (int s = 0; s < 4; ++s) {
                        uint32_t en0 = (k > 0 || s > 0) ? 1u : 0u;
                        mma_f16_ss(dt, dAh + s*2, dWh + s*2, GEMM_IDESC, en0);
                        mma_f16_ss(dt, dAl + s*2, dWh + s*2, GEMM_IDESC, 1u);
                        mma_f16_ss(dt, dAh + s*2, dWl + s*2, GEMM_IDESC, 1u);
                    }
                }
                TCGEN05_COMMIT(mb + b * 8);
            }
        }
        if (STAGES == 2) {
            if (k + 2 < 16) {
                MBARRIER_WAIT_PARITY(mb + b * 8, phase[b]);
                phase[b] ^= 1;
                load_chunk<NTILE>(Ah, Al, Wh, Wl, tiles + b * STAGE_B, m0, n0,
                                  (k + 2) * 64, tid);
            }
        } else {
            if (k >= 1 && (k - 1 + STAGES) < 16) {
                int pb = (k - 1) % STAGES;
                MBARRIER_WAIT_PARITY(mb + pb * 8, phase[pb]);
                phase[pb] ^= 1;
                load_chunk<NTILE>(Ah, Al, Wh, Wl, tiles + pb * STAGE_B, m0, n0,
                                  (k - 1 + STAGES) * 64, tid);
            }
        }
    }
    {   // wait for chunk 15's commit (tensor pipe is in-order -> all MMAs done)
        int bl = 15 % STAGES;
        MBARRIER_WAIT_PARITY(mb + bl * 8, phase[bl]);
    }
    TCGEN05_FENCE_AFTER();

    if (wid < 4) {
        int r = wid * 32 + lane;
        size_t rowbase = (size_t)(m0 + r) * N + n0;
        #pragma unroll
        for (int c0 = 0; c0 < NTILE; c0 += 32) {
            uint32_t regs[32];
            TCGEN05_LD_X32(regs, tmem + c0);
            TCGEN05_WAIT_LD();
            #pragma unroll
            for (int j = 0; j < 32; j += 4) {
                float4 o;
                o.x = __uint_as_float(regs[j+0]) + bias_s[c0+j+0];
                o.y = __uint_as_float(regs[j+1]) + bias_s[c0+j+1];
                o.z = __uint_as_float(regs[j+2]) + bias_s[c0+j+2];
                o.w = __uint_as_float(regs[j+3]) + bias_s[c0+j+3];
                if (C) {
                    float* cp = C + rowbase + c0 + j;
                    if (streamC) st_cs_f4(cp, o);
                    else *reinterpret_cast<float4*>(cp) = o;
                }
                if (bfHi) store_hilo4(bfHi, bfLo, rowbase + c0 + j, o);
            }
        }
        TCGEN05_FENCE_BEFORE();
    }
    __syncthreads();
    if (wid == 0) {
        TCGEN05_RELINQ();
        TCGEN05_DEALLOC(tmem, NTILE);
    }
#endif // HAS_TCGEN05
}

// ---------------- 1. bucket mean pool -> init hi/lo ----------------
__global__ void pool_kernel(const float* __restrict__ proj,
                            const int* __restrict__ bnd32,
                            const float* __restrict__ mask,
                            int hiId, int loId)
{
    int blk = blockIdx.x;
    int b = blk / NK;
    int s, e;
    get_bounds(bnd32, blk, s, e);
    float m = mask[blk];
    float4 a0 = make_float4(0.f, 0.f, 0.f, 0.f);
    float4 a1 = make_float4(0.f, 0.f, 0.f, 0.f);
    int cnt = e - s;
    if (m > 0.f && cnt > 0) {
        int t = s;
        for (; t + 1 < e; t += 2) {
            const float4* p0 = reinterpret_cast<const float4*>(proj + ((size_t)b*NT + t)*HDIM);
            const float4* p1 = reinterpret_cast<const float4*>(proj + ((size_t)b*NT + t + 1)*HDIM);
            float4 v0 = p0[threadIdx.x], v1 = p1[threadIdx.x];
            a0.x += v0.x; a0.y += v0.y; a0.z += v0.z; a0.w += v0.w;
            a1.x += v1.x; a1.y += v1.y; a1.z += v1.z; a1.w += v1.w;
        }
        if (t < e) {
            const float4* p0 = reinterpret_cast<const float4*>(proj + ((size_t)b*NT + t)*HDIM);
            float4 v0 = p0[threadIdx.x];
            a0.x += v0.x; a0.y += v0.y; a0.z += v0.z; a0.w += v0.w;
        }
        float inv = 1.f / (float)cnt;
        a0.x = (a0.x + a1.x) * inv; a0.y = (a0.y + a1.y) * inv;
        a0.z = (a0.z + a1.z) * inv; a0.w = (a0.w + a1.w) * inv;
    }
    store_hilo4(bufb(hiId), bufb(loId), (size_t)blk*HDIM + threadIdx.x*4, a0);
}

// ---------------- windowed cross attention -> attno hi/lo ----------------
__global__ void cross_attn_kernel(const int* __restrict__ bnd32,
                                  const float* __restrict__ mask,
                                  int hiId, int loId)
{
    int blk  = blockIdx.x;
    int b    = blk / NK;
    int head = threadIdx.x >> 5;
    int lane = threadIdx.x & 31;
    int s0, e0;
    get_bounds(bnd32, blk, s0, e0);
    int w = min(e0 - s0, 32);
    bool valid = (mask[blk] > 0.5f) && (w > 0);

    __shared__ __align__(16) float qsm[NHD][DH];
    const float4* qp4 = reinterpret_cast<const float4*>(g_qh + (size_t)blk*HDIM + head*DH);
    float4 qv = qp4[lane];
    qsm[head][lane*4+0] = qv.x; qsm[head][lane*4+1] = qv.y;
    qsm[head][lane*4+2] = qv.z; qsm[head][lane*4+3] = qv.w;
    __syncwarp();

    float sc = -INFINITY;
    if (valid && lane < w) {
        const float4* kp4 = reinterpret_cast<const float4*>(
            g_kvh + ((size_t)b*NT + s0 + lane) * (2*HDIM) + head*DH);
        const float4* q4 = reinterpret_cast<const float4*>(qsm[head]);
        float a = 0.f;
        #pragma unroll 8
        for (int d = 0; d < 32; ++d) {
            float4 kv = kp4[d], q2 = q4[d];
            a += q2.x*kv.x + q2.y*kv.y + q2.z*kv.z + q2.w*kv.w;
        }
        sc = a * 0.08838834764831845f;
    }
    float mx = wred_max(sc);
    float pj = (sc == -INFINITY) ? 0.f : __expf(sc - mx);
    float ss = wred_sum(pj);
    float p  = (valid && ss > 0.f) ? (pj / ss) : 0.f;

    float4 o = make_float4(0.f, 0.f, 0.f, 0.f);
    for (int t = 0; t < w; ++t) {
        float pt = __shfl_sync(0xffffffffu, p, t);
        const float4* vp4 = reinterpret_cast<const float4*>(
            g_kvh + ((size_t)b*NT + s0 + t) * (2*HDIM) + HDIM + head*DH);
        float4 v = vp4[lane];
        o.x += pt*v.x; o.y += pt*v.y; o.z += pt*v.z; o.w += pt*v.w;
    }
    store_hilo4(bufb(hiId), bufb(loId), (size_t)blk*HDIM + head*DH + lane*4, o);
}

// ---------------- fused residual-add + LayerNorm ----------------
__global__ void add_ln_kernel(int Xid, int Rid,
                              const float* __restrict__ g, const float* __restrict__ bet,
                              float* __restrict__ Oext, int Oid, int bfHiId, int bfLoId)
{
    const float* X = bufp(Xid, nullptr);
    const float* R = bufp(Rid, nullptr);
    float* out = bufp(Oid, Oext);
    int row = blockIdx.x;
    int tid = threadIdx.x;
    int lane = tid & 31, wid = tid >> 5;
    __shared__ float sm[8];

    float4 x = reinterpret_cast<const float4*>(X + (size_t)row*HDIM)[tid];
    float4 r = reinterpret_cast<const float4*>(R + (size_t)row*HDIM)[tid];
    x.x += r.x; x.y += r.y; x.z += r.z; x.w += r.w;

    float s = x.x + x.y + x.z + x.w;
    s = wred_sum(s);
    if (!lane) sm[wid] = s;
    __syncthreads();
    float tot = 0.f;
    #pragma unroll
    for (int i = 0; i < 8; ++i) tot += sm[i];
    float mean = tot * (1.f / HDIM);

    float d0 = x.x-mean, d1 = x.y-mean, d2 = x.z-mean, d3 = x.w-mean;
    float vloc = d0*d0 + d1*d1 + d2*d2 + d3*d3;
    __syncthreads();
    vloc = wred_sum(vloc);
    if (!lane) sm[wid] = vloc;
    __syncthreads();
    float var = 0.f;
    #pragma unroll
    for (int i = 0; i < 8; ++i) var += sm[i];
    var *= (1.f / HDIM);
    float inv = rsqrtf(var + 1e-5f);

    float4 gg = reinterpret_cast<const float4*>(g)[tid];
    float4 bb = reinterpret_cast<const float4*>(bet)[tid];
    float4 o;
    o.x = d0*inv*gg.x + bb.x;
    o.y = d1*inv*gg.y + bb.y;
    o.z = d2*inv*gg.z + bb.z;
    o.w = d3*inv*gg.w + bb.w;
    size_t idx = (size_t)row*HDIM + tid*4;
    *reinterpret_cast<float4*>(out + idx) = o;
    if (bfHiId >= 0) store_hilo4(bufb(bfHiId), bufb(bfLoId), idx, o);
}

// ---------------- causal self attention, block per (head, b) ----------------
#define SA_PAD 132
#define SA_SMEM ((2*NK*SA_PAD + 16*SA_PAD + 16*NK + NK) * 4)

__global__ __launch_bounds__(512, 1)
void self_attn_kernel(const float* __restrict__ mask, int hiId, int loId)
{
    extern __shared__ float sam[];
    float* Ksm = sam;
    float* Vsm = Ksm + NK*SA_PAD;
    float* qsm = Vsm + NK*SA_PAD;
    float* psm = qsm + 16*SA_PAD;
    float* msm = psm + 16*NK;

    int head = blockIdx.x, b = blockIdx.y;
    int tid = threadIdx.x, lane = tid & 31, w = tid >> 5;
    const float* base = g_saqkv + (size_t)(b*NK) * 3*HDIM;

    for (int idx = tid; idx < NK*DH; idx += 512) {
        int row = idx >> 7, col = idx & 127;
        Ksm[row*SA_PAD + col] = base[(size_t)row*3*HDIM +   HDIM + head*DH + col];
        Vsm[row*SA_PAD + col] = base[(size_t)row*3*HDIM + 2*HDIM + head*DH + col];
    }
    if (tid < NK) msm[tid] = mask[b*NK + tid];
    __syncthreads();

    __nv_bfloat16* ctxHi = bufb(hiId);
    __nv_bfloat16* ctxLo = bufb(loId);

    for (int qi = w; qi < NK; qi += 16) {
        float4 qv = *reinterpret_cast<const float4*>(
            base + (size_t)qi*3*HDIM + head*DH + lane*4);
        *reinterpret_cast<float4*>(qsm + w*SA_PAD + lane*4) = qv;
        __syncwarp();

        float sc[4];
        #pragma unroll
        for (int kk = 0; kk < 4; ++kk) {
            int j = lane + kk*32;
            float a = 0.f;
            const float* qr = qsm + w*SA_PAD;
            const float* kr = Ksm + j*SA_PAD;
            #pragma unroll 8
            for (int d = 0; d < 128; ++d) a += qr[d] * kr[d];
            bool ok = (j <= qi) && (msm[j] > 0.5f);
            sc[kk] = ok ? a * 0.08838834764831845f : -INFINITY;
        }
        float mx = fmaxf(fmaxf(sc[0], sc[1]), fmaxf(sc[2], sc[3]));
        mx = wred_max(mx);
        float psum = 0.f, pr[4];
        #pragma unroll
        for (int kk = 0; kk < 4; ++kk) {
            pr[kk] = (sc[kk] == -INFINITY) ? 0.f : __expf(sc[kk] - mx);
            psum += pr[kk];
        }
        psum = wred_sum(psum);
        float inv = (psum > 0.f) ? 1.f / psum : 0.f;
        #pragma unroll
        for (int kk = 0; kk < 4; ++kk)
            psm[w*NK + kk*32 + lane] = pr[kk] * inv;
        __syncwarp();

        float4 o = make_float4(0.f, 0.f, 0.f, 0.f);
        for (int j = 0; j <= qi; ++j) {
            float p = psm[w*NK + j];
            float4 v = *reinterpret_cast<const float4*>(Vsm + j*SA_PAD + lane*4);
            o.x += p*v.x; o.y += p*v.y; o.z += p*v.z; o.w += p*v.w;
        }
        store_hilo4(ctxHi, ctxLo, (size_t)(b*NK + qi)*HDIM + head*DH + lane*4, o);
        __syncwarp();
    }
}

// ---------------- launch ----------------
extern "C" void kernel_launch(void* const* d_in, const int* in_sizes, int n_in,
                              void* d_out, int out_size)
{
    const float* projected  = (const float*)d_in[0];
    const int*   bnd32      = (const int*)d_in[1];
    const float* slot_mask  = (const float*)d_in[2];
    const float* qp_w   = (const float*)d_in[3];
    const float* qp_b   = (const float*)d_in[4];
    const float* ca_in_w  = (const float*)d_in[5];
    const float* ca_in_b  = (const float*)d_in[6];
    const float* ca_out_w = (const float*)d_in[7];
    const float* ca_out_b = (const float*)d_in[8];
    const float* cn_g   = (const float*)d_in[9];
    const float* cn_b   = (const float*)d_in[10];
    const float* sa_in_w  = (const float*)d_in[11];
    const float* sa_in_b  = (const float*)d_in[12];
    const float* sa_out_w = (const float*)d_in[13];
    const float* sa_out_b = (const float*)d_in[14];
    const float* on_g   = (const float*)d_in[15];
    const float* on_b   = (const float*)d_in[16];
    float* out = (float*)d_out;

    static int attr_set = 0;
    static cudaStream_t s1 = nullptr, s2 = nullptr;
    static cudaEvent_t evF = nullptr, evW = nullptr, evPool = nullptr, evKVH = nullptr;
    if (!attr_set) {
        cudaFuncSetAttribute(gemm_tc<128,3>, cudaFuncAttributeMaxDynamicSharedMemorySize, GEMM_SMEM);
        cudaFuncSetAttribute(gemm_tc<256,2>, cudaFuncAttributeMaxDynamicSharedMemorySize, GEMM_SMEM);
        cudaFuncSetAttribute(self_attn_kernel, cudaFuncAttributeMaxDynamicSharedMemorySize, SA_SMEM);
        cudaStreamCreateWithFlags(&s1, cudaStreamNonBlocking);
        cudaStreamCreateWithFlags(&s2, cudaStreamNonBlocking);
        cudaEventCreateWithFlags(&evF,    cudaEventDisableTiming);
        cudaEventCreateWithFlags(&evW,    cudaEventDisableTiming);
        cudaEventCreateWithFlags(&evPool, cudaEventDisableTiming);
        cudaEventCreateWithFlags(&evKVH,  cudaEventDisableTiming);
        attr_set = 1;
    }

    // ---- fork ----
    cudaEventRecord(evF, 0);
    cudaStreamWaitEvent(s1, evF, 0);
    cudaStreamWaitEvent(s2, evF, 0);

    // s1: proj hi/lo, then (after weights) the BIG kvh GEMM — runs concurrently
    //     with the slot-side chain L4/L5 on the default stream.
    conv_hilo<<<(int)(((size_t)MT*HDIM)/1024), 256, 0, s1>>>(projected, 0, 1);

    // s2: bucket mean pool -> act(2,3) (needed by L4)
    pool_kernel<<<MS, 256, 0, s2>>>(projected, bnd32, slot_mask, 2, 3);
    cudaEventRecord(evPool, s2);

    // default: all weights hi/lo (fused); needed by all GEMMs
    conv_w_all<<<9216, 256>>>(qp_w, ca_in_w, ca_out_w, sa_in_w, sa_out_w);
    cudaEventRecord(evW, 0);

    // s1: big kvh GEMM (needs proj conv [stream order] + weights [evW])
    cudaStreamWaitEvent(s1, evW, 0);
    gemm_tc<256,2><<<dim3(2*HDIM/256, MT/128), 256, GEMM_SMEM, s1>>>(
        0, 1, 6, 7, (size_t)HDIM*HDIM, ca_in_b + HDIM, 3, -1, -1, 2*HDIM, 1);
    cudaEventRecord(evKVH, s1);

    // default: L4/L5 run concurrently with the big GEMM.
    cudaStreamWaitEvent(0, evPool, 0);
    gemm_tc<128,3><<<dim3(HDIM/128, MS/128), 256, GEMM_SMEM>>>(2, 3, 4, 5, 0, qp_b, 1, 14, 15, HDIM, 0);
    gemm_tc<128,3><<<dim3(HDIM/128, MS/128), 256, GEMM_SMEM>>>(14, 15, 6, 7, 0, ca_in_b, 2, -1, -1, HDIM, 0);

    // join: cross attention needs qh (default order) + kvh (evKVH)
    cudaStreamWaitEvent(0, evKVH, 0);
    cross_attn_kernel<<<MS, 256>>>(bnd32, slot_mask, 2, 3);
    // attn_out = attno @ ca_out_w^T -> id5
    gemm_tc<128,3><<<dim3(HDIM/128, MS/128), 256, GEMM_SMEM>>>(2, 3, 8, 9, 0, ca_out_b, 5, -1, -1, HDIM, 0);
    // slots = LN(attn_out + queries) -> id6 + act2(14,15)
    add_ln_kernel<<<MS, 256>>>(5, 1, cn_g, cn_b, nullptr, 6, 14, 15);
    // sa_qkv = slots @ sa_in_w^T -> id7
    gemm_tc<128,3><<<dim3(3*HDIM/128, MS/128), 256, GEMM_SMEM>>>(14, 15, 10, 11, 0, sa_in_b, 7, -1, -1, 3*HDIM, 0);
    // causal self attention -> act(2,3)
    self_attn_kernel<<<dim3(NHD, NB), 512, SA_SMEM>>>(slot_mask, 2, 3);
    // ctx_out = ctx @ sa_out_w^T -> id9
    gemm_tc<128,3><<<dim3(HDIM/128, MS/128), 256, GEMM_SMEM>>>(2, 3, 12, 13, 0, sa_out_b, 9, -1, -1, HDIM, 0);
    // out = LN(ctx_out + slots)
    add_ln_kernel<<<MS, 256>>>(9, 6, on_g, on_b, out, -1, -1, -1);
}